// round 3
// baseline (speedup 1.0000x reference)
#include <cuda_runtime.h>
#include <math.h>

// ---------------------------------------------------------------------------
// TokenEmbedding: content embeddings + positional maps via binary-path
// products of two orthogonal generators G[b] = expm(P_b^T - P_b).
//
// Table strategy: only entries p < 64 are materialized (1 MB, L2-resident,
// also stored tf32-decomposed). For p >= 64 the gather kernel computes
// M[p] = M[32|(p&31)] @ M[p>>5] on tensor cores and writes straight to out.
//
// Output layout (float32):
//   [0, n_tokens*64)   content [B,S,64]
//   [n_tokens*64, ...) maps    [B,S,64,64]
// ---------------------------------------------------------------------------

#define NPOS 2048
#define MSZ  4096      // 64*64 elements per matrix
#define SMS  66        // padded smem row stride for build kernels (floats)
#define SMAT (64 * SMS)
#define SA   68        // gather smem stride for A operand (68 % 32 == 4)
#define SB   72        // gather smem stride for B operand (72 % 32 == 8)

__device__ __align__(16) float    g_M[64 * MSZ];      // small table, fp32
__device__ __align__(16) unsigned g_Thi[64 * MSZ];    // tf32 hi bits
__device__ __align__(16) unsigned g_Tlo[64 * MSZ];    // tf32 lo bits
__device__ __align__(16) float    g_G[2 * MSZ];

// ---------------------------------------------------------------------------
// tf32 helpers
// ---------------------------------------------------------------------------
__device__ __forceinline__ unsigned f2tf32(float x) {
    unsigned r;
    asm("cvt.rna.tf32.f32 %0, %1;" : "=r"(r) : "f"(x));
    return r;
}

__device__ __forceinline__ void mma_tf32(float& c0, float& c1, float& c2, float& c3,
                                         unsigned a0, unsigned a1, unsigned a2, unsigned a3,
                                         unsigned b0, unsigned b1) {
    asm volatile(
        "mma.sync.aligned.m16n8k8.row.col.f32.tf32.tf32.f32 "
        "{%0,%1,%2,%3}, {%4,%5,%6,%7}, {%8,%9}, {%0,%1,%2,%3};\n"
        : "+f"(c0), "+f"(c1), "+f"(c2), "+f"(c3)
        : "r"(a0), "r"(a1), "r"(a2), "r"(a3), "r"(b0), "r"(b1));
}

// ---------------------------------------------------------------------------
// Build-phase 64x64x64 matmul (on-the-fly 3xTF32 split), A/B smem stride SMS,
// C stride CS. 256 threads = 8 warps. Caller syncs.
// ---------------------------------------------------------------------------
__device__ __forceinline__ void mm64(float* __restrict__ C, int CS,
                                     const float* __restrict__ A,
                                     const float* __restrict__ B) {
    const int lane = threadIdx.x & 31;
    const int w    = threadIdx.x >> 5;
    const int g    = lane >> 2;
    const int t    = lane & 3;
    const int m0   = (w & 3) * 16;
    const int n0   = (w >> 2) * 32;

    float acc[4][4];
#pragma unroll
    for (int nt = 0; nt < 4; nt++)
#pragma unroll
        for (int c = 0; c < 4; c++) acc[nt][c] = 0.0f;

#pragma unroll
    for (int k0 = 0; k0 < 64; k0 += 8) {
        float af0 = A[(m0 + g)     * SMS + k0 + t];
        float af1 = A[(m0 + g + 8) * SMS + k0 + t];
        float af2 = A[(m0 + g)     * SMS + k0 + t + 4];
        float af3 = A[(m0 + g + 8) * SMS + k0 + t + 4];
        unsigned ah0 = f2tf32(af0), ah1 = f2tf32(af1);
        unsigned ah2 = f2tf32(af2), ah3 = f2tf32(af3);
        unsigned al0 = f2tf32(af0 - __uint_as_float(ah0));
        unsigned al1 = f2tf32(af1 - __uint_as_float(ah1));
        unsigned al2 = f2tf32(af2 - __uint_as_float(ah2));
        unsigned al3 = f2tf32(af3 - __uint_as_float(ah3));

#pragma unroll
        for (int nt = 0; nt < 4; nt++) {
            const int nc = n0 + nt * 8 + g;
            float bf0 = B[(k0 + t)     * SMS + nc];
            float bf1 = B[(k0 + t + 4) * SMS + nc];
            unsigned bh0 = f2tf32(bf0), bh1 = f2tf32(bf1);
            unsigned bl0 = f2tf32(bf0 - __uint_as_float(bh0));
            unsigned bl1 = f2tf32(bf1 - __uint_as_float(bh1));

            mma_tf32(acc[nt][0], acc[nt][1], acc[nt][2], acc[nt][3],
                     ah0, ah1, ah2, ah3, bh0, bh1);
            mma_tf32(acc[nt][0], acc[nt][1], acc[nt][2], acc[nt][3],
                     ah0, ah1, ah2, ah3, bl0, bl1);
            mma_tf32(acc[nt][0], acc[nt][1], acc[nt][2], acc[nt][3],
                     al0, al1, al2, al3, bh0, bh1);
        }
    }

#pragma unroll
    for (int nt = 0; nt < 4; nt++) {
        const int col = n0 + nt * 8 + 2 * t;
        *(float2*)(C + (m0 + g)     * CS + col) = make_float2(acc[nt][0], acc[nt][1]);
        *(float2*)(C + (m0 + g + 8) * CS + col) = make_float2(acc[nt][2], acc[nt][3]);
    }
}

// ---------------------------------------------------------------------------
// Kernel 1: expm. Block b computes G[b] = expm(P_b^T - P_b); seeds M[0]=M[1]=I.
// ---------------------------------------------------------------------------
__global__ void __launch_bounds__(256, 1)
expm_kernel(const float* __restrict__ prim_raw) {
    extern __shared__ float sm[];
    float* Bb = sm;
    float* B2 = sm + SMAT;
    float* B3 = sm + 2 * SMAT;
    float* X  = sm + 3 * SMAT;
    float* Y  = sm + 4 * SMAT;
    __shared__ float colsum[64];
    __shared__ int s_sh;

    const int b = blockIdx.x;
    const int tid = threadIdx.x;
    const float* P = prim_raw + b * MSZ;

    for (int tidx = tid; tidx < MSZ; tidx += 256) {
        int i = tidx >> 6, j = tidx & 63;
        Bb[i * SMS + j] = P[j * 64 + i] - P[tidx];
    }
    __syncthreads();

    if (tid < 64) {
        float s = 0.0f;
        for (int i = 0; i < 64; i++) s += fabsf(Bb[i * SMS + tid]);
        colsum[tid] = s;
    }
    __syncthreads();
    if (tid == 0) {
        float nm = 0.0f;
        for (int j = 0; j < 64; j++) nm = fmaxf(nm, colsum[j]);
        int s = 0;
        while (nm > 1.0f && s < 14) { nm *= 0.5f; s++; }
        s_sh = s;
    }
    __syncthreads();
    const int s = s_sh;
    const float scale = ldexpf(1.0f, -s);
    for (int tidx = tid; tidx < MSZ; tidx += 256) {
        int i = tidx >> 6, j = tidx & 63;
        Bb[i * SMS + j] *= scale;
    }
    __syncthreads();

    mm64(B2, SMS, Bb, Bb);
    __syncthreads();
    mm64(B3, SMS, Bb, B2);
    __syncthreads();

    for (int tidx = tid; tidx < MSZ; tidx += 256) {
        int i = tidx >> 6, j = tidx & 63;
        int k = i * SMS + j;
        float d = (i == j) ? (1.0f / 720.0f) : 0.0f;
        X[k] = d + Bb[k] * (1.0f / 5040.0f) + B2[k] * (1.0f / 40320.0f)
                 + B3[k] * (1.0f / 362880.0f);
    }
    __syncthreads();
    mm64(Y, SMS, B3, X);
    __syncthreads();
    for (int tidx = tid; tidx < MSZ; tidx += 256) {
        int i = tidx >> 6, j = tidx & 63;
        int k = i * SMS + j;
        float d = (i == j) ? (1.0f / 6.0f) : 0.0f;
        X[k] = d + Bb[k] * (1.0f / 24.0f) + B2[k] * (1.0f / 120.0f) + Y[k];
    }
    __syncthreads();
    mm64(Y, SMS, B3, X);
    __syncthreads();
    for (int tidx = tid; tidx < MSZ; tidx += 256) {
        int i = tidx >> 6, j = tidx & 63;
        int k = i * SMS + j;
        float d = (i == j) ? 1.0f : 0.0f;
        X[k] = d + Bb[k] + B2[k] * 0.5f + Y[k];
    }
    __syncthreads();

    float* Xp = X;
    float* Yp = Y;
    for (int k = 0; k < s; k++) {
        mm64(Yp, SMS, Xp, Xp);
        __syncthreads();
        float* tp = Xp; Xp = Yp; Yp = tp;
    }

    for (int tidx = tid; tidx < MSZ; tidx += 256) {
        int i = tidx >> 6, j = tidx & 63;
        g_G[b * MSZ + tidx] = Xp[i * SMS + j];
        g_M[b * MSZ + tidx] = (i == j) ? 1.0f : 0.0f;   // M[0], M[1] = I
    }
}

// ---------------------------------------------------------------------------
// Kernel 2: M[p] for p in [2,64) (chain of <=4 matmuls), stored fp32 AND
// tf32-decomposed (hi/lo) for the fused gather.
// ---------------------------------------------------------------------------
__global__ void __launch_bounds__(256, 1)
table_small_kernel() {
    extern __shared__ float sm[];
    float* X  = sm;
    float* Gs = sm + SMAT;
    float* Y  = sm + 2 * SMAT;
    const int p = blockIdx.x + 2;
    const int tid = threadIdx.x;
    const int m = 32 - __clz(p);

    for (int tidx = tid; tidx < MSZ; tidx += 256) {
        int i = tidx >> 6, j = tidx & 63;
        X[i * SMS + j] = g_G[(p & 1) * MSZ + tidx];
    }
    __syncthreads();
    for (int st = 1; st <= m - 2; st++) {
        const int bit = (p >> st) & 1;
        for (int tidx = tid; tidx < MSZ; tidx += 256) {
            int i = tidx >> 6, j = tidx & 63;
            Gs[i * SMS + j] = g_G[bit * MSZ + tidx];
        }
        __syncthreads();
        mm64(Y, SMS, X, Gs);
        __syncthreads();
        float* tp = X; X = Y; Y = tp;
    }
    for (int tidx = tid; tidx < MSZ; tidx += 256) {
        int i = tidx >> 6, j = tidx & 63;
        float v = X[i * SMS + j];
        g_M[(size_t)p * MSZ + tidx] = v;
        unsigned h = f2tf32(v);
        g_Thi[(size_t)p * MSZ + tidx] = h;
        g_Tlo[(size_t)p * MSZ + tidx] = f2tf32(v - __uint_as_float(h));
    }
}

// ---------------------------------------------------------------------------
// Kernel 3 (fused): per token, either copy M[p] (p<64) or compute
// M[lo] @ M[hi] from the pre-decomposed table, writing straight to out.
// Also emits the masked content embedding.
// Dynamic smem: 2*(64*SA) + 2*(64*SB) uints = 71,680 B.
// ---------------------------------------------------------------------------
__global__ void __launch_bounds__(256, 1)
gather_fused_kernel(const int* __restrict__ token_types,
                    const int* __restrict__ token_values,
                    const int* __restrict__ node_positions,
                    const float* __restrict__ embed_table,
                    float* __restrict__ out,
                    int maps_off) {
    extern __shared__ unsigned usm[];
    unsigned* Ahi = usm;
    unsigned* Alo = usm + 64 * SA;
    unsigned* Bhi = usm + 2 * 64 * SA;
    unsigned* Blo = usm + 2 * 64 * SA + 64 * SB;

    const int token = blockIdx.x;
    const int tid = threadIdx.x;
    const int p = node_positions[token];
    float* dstm = out + (size_t)maps_off + (size_t)token * MSZ;

    // content embedding (64 lanes)
    if (tid < 64) {
        const int T = token_types[token];
        const int V = token_values[token];
        int idx;
        bool valid = true;
        if (T == 0)      idx = 0;
        else if (T == 1) idx = V + 1;
        else if (T == 2) idx = V + 5;
        else if (T == 4) idx = 8;
        else if (T == 3 && V == -1) idx = 10;
        else { idx = 0; valid = false; }
        out[(size_t)token * 64 + tid] = valid ? embed_table[idx * 64 + tid] : 0.0f;
    }

    if (p < 64) {
        // direct copy of the (L2-resident) small-table entry
        const float4* src = (const float4*)(g_M + (size_t)p * MSZ);
        float4* dst = (float4*)dstm;
#pragma unroll
        for (int i = 0; i < 4; i++) {
            float4 v = __ldg(&src[tid + i * 256]);
            __stcs(&dst[tid + i * 256], v);
        }
        return;
    }

    const int lo = (p & 31) | 32;
    const int hi = p >> 5;
    const uint4* sAh = (const uint4*)(g_Thi + (size_t)lo * MSZ);
    const uint4* sAl = (const uint4*)(g_Tlo + (size_t)lo * MSZ);
    const uint4* sBh = (const uint4*)(g_Thi + (size_t)hi * MSZ);
    const uint4* sBl = (const uint4*)(g_Tlo + (size_t)hi * MSZ);

    // stage operands into padded smem (16 uint4 per 64-elem row)
#pragma unroll
    for (int it = 0; it < 4; it++) {
        int idx = tid + it * 256;            // 0..1023
        int row = idx >> 4;
        int col = (idx & 15) << 2;
        *(uint4*)(Ahi + row * SA + col) = __ldg(&sAh[idx]);
        *(uint4*)(Alo + row * SA + col) = __ldg(&sAl[idx]);
        *(uint4*)(Bhi + row * SB + col) = __ldg(&sBh[idx]);
        *(uint4*)(Blo + row * SB + col) = __ldg(&sBl[idx]);
    }
    __syncthreads();

    // 64x64x64 3xTF32 matmul, output straight to global
    const int lane = tid & 31;
    const int w    = tid >> 5;
    const int g    = lane >> 2;
    const int t    = lane & 3;
    const int m0   = (w & 3) * 16;
    const int n0   = (w >> 2) * 32;

    float acc[4][4];
#pragma unroll
    for (int nt = 0; nt < 4; nt++)
#pragma unroll
        for (int c = 0; c < 4; c++) acc[nt][c] = 0.0f;

#pragma unroll
    for (int k0 = 0; k0 < 64; k0 += 8) {
        unsigned ah0 = Ahi[(m0 + g)     * SA + k0 + t];
        unsigned ah1 = Ahi[(m0 + g + 8) * SA + k0 + t];
        unsigned ah2 = Ahi[(m0 + g)     * SA + k0 + t + 4];
        unsigned ah3 = Ahi[(m0 + g + 8) * SA + k0 + t + 4];
        unsigned al0 = Alo[(m0 + g)     * SA + k0 + t];
        unsigned al1 = Alo[(m0 + g + 8) * SA + k0 + t];
        unsigned al2 = Alo[(m0 + g)     * SA + k0 + t + 4];
        unsigned al3 = Alo[(m0 + g + 8) * SA + k0 + t + 4];

#pragma unroll
        for (int nt = 0; nt < 4; nt++) {
            const int nc = n0 + nt * 8 + g;
            unsigned bh0 = Bhi[(k0 + t)     * SB + nc];
            unsigned bh1 = Bhi[(k0 + t + 4) * SB + nc];
            unsigned bl0 = Blo[(k0 + t)     * SB + nc];
            unsigned bl1 = Blo[(k0 + t + 4) * SB + nc];

            mma_tf32(acc[nt][0], acc[nt][1], acc[nt][2], acc[nt][3],
                     ah0, ah1, ah2, ah3, bh0, bh1);
            mma_tf32(acc[nt][0], acc[nt][1], acc[nt][2], acc[nt][3],
                     ah0, ah1, ah2, ah3, bl0, bl1);
            mma_tf32(acc[nt][0], acc[nt][1], acc[nt][2], acc[nt][3],
                     al0, al1, al2, al3, bh0, bh1);
        }
    }

#pragma unroll
    for (int nt = 0; nt < 4; nt++) {
        const int col = n0 + nt * 8 + 2 * t;
        __stcs((float2*)(dstm + (m0 + g)     * 64 + col),
               make_float2(acc[nt][0], acc[nt][1]));
        __stcs((float2*)(dstm + (m0 + g + 8) * 64 + col),
               make_float2(acc[nt][2], acc[nt][3]));
    }
}

// ---------------------------------------------------------------------------
extern "C" void kernel_launch(void* const* d_in, const int* in_sizes, int n_in,
                              void* d_out, int out_size) {
    const int*   token_types  = (const int*)d_in[0];
    const int*   token_values = (const int*)d_in[1];
    const int*   node_pos     = (const int*)d_in[2];
    const float* embed_table  = (const float*)d_in[3];
    const float* prim_raw     = (const float*)d_in[4];
    float* out = (float*)d_out;

    const int n_tokens = in_sizes[0];
    const int maps_off = n_tokens * 64;
    const int gather_smem = (2 * 64 * SA + 2 * 64 * SB) * 4;

    cudaFuncSetAttribute(expm_kernel,
                         cudaFuncAttributeMaxDynamicSharedMemorySize, 5 * SMAT * 4);
    cudaFuncSetAttribute(table_small_kernel,
                         cudaFuncAttributeMaxDynamicSharedMemorySize, 3 * SMAT * 4);
    cudaFuncSetAttribute(gather_fused_kernel,
                         cudaFuncAttributeMaxDynamicSharedMemorySize, gather_smem);

    expm_kernel<<<2, 256, 5 * SMAT * 4>>>(prim_raw);
    table_small_kernel<<<62, 256, 3 * SMAT * 4>>>();
    gather_fused_kernel<<<n_tokens, 256, gather_smem>>>(
        token_types, token_values, node_pos, embed_table, out, maps_off);
}

// round 4
// speedup vs baseline: 1.1122x; 1.1122x over previous
#include <cuda_runtime.h>
#include <math.h>

// ---------------------------------------------------------------------------
// TokenEmbedding: content embeddings + positional maps via binary-path
// products of two orthogonal generators G[b] = expm(P_b^T - P_b).
// All matmuls: 3xTF32 mma.sync with PRE-SPLIT hi/lo operands (uint2 per elem).
//
// Output layout (float32):
//   [0, n_tokens*64)   content [B,S,64]
//   [n_tokens*64, ...) maps    [B,S,64,64]
// ---------------------------------------------------------------------------

#define NPOS 2048
#define MSZ  4096              // 64*64 elements per matrix
#define S2   68                // smem row stride in uint2 elements
#define MATU2 (64 * S2)        // uint2 elements per smem matrix (34,816 B)

__device__ __align__(16) float g_M[NPOS * MSZ];   // fp32 table (32 MB)
__device__ __align__(16) uint2 g_Mu2[64 * MSZ];   // presplit M[0..63] (2 MB)
__device__ __align__(16) uint2 g_Gu2[2 * MSZ];    // presplit generators

// ---------------------------------------------------------------------------
__device__ __forceinline__ unsigned f2tf32(float x) {
    unsigned r;
    asm("cvt.rna.tf32.f32 %0, %1;" : "=r"(r) : "f"(x));
    return r;
}
__device__ __forceinline__ uint2 split2(float f) {
    unsigned h = f2tf32(f);
    return make_uint2(h, f2tf32(f - __uint_as_float(h)));
}
__device__ __forceinline__ float joinf(uint2 v) {
    return __uint_as_float(v.x) + __uint_as_float(v.y);
}

__device__ __forceinline__ void mma_tf32(float& c0, float& c1, float& c2, float& c3,
                                         unsigned a0, unsigned a1, unsigned a2, unsigned a3,
                                         unsigned b0, unsigned b1) {
    asm volatile(
        "mma.sync.aligned.m16n8k8.row.col.f32.tf32.tf32.f32 "
        "{%0,%1,%2,%3}, {%4,%5,%6,%7}, {%8,%9}, {%0,%1,%2,%3};\n"
        : "+f"(c0), "+f"(c1), "+f"(c2), "+f"(c3)
        : "r"(a0), "r"(a1), "r"(a2), "r"(a3), "r"(b0), "r"(b1));
}

// ---------------------------------------------------------------------------
// 64x64x64 3xTF32 matmul with presplit smem operands (stride S2 uint2).
// 256 threads = 8 warps; warp w -> C[(w&3)*16.., (w>>2)*32..].
// WPS: write presplit result to Cps (stride S2). WF: write fp32 to Cf (stride CS).
// Caller handles __syncthreads.
// ---------------------------------------------------------------------------
template<bool WPS, bool WF>
__device__ __forceinline__ void mm64ps(uint2* __restrict__ Cps,
                                       float* __restrict__ Cf, int CS,
                                       const uint2* __restrict__ A,
                                       const uint2* __restrict__ B) {
    const int lane = threadIdx.x & 31;
    const int w    = threadIdx.x >> 5;
    const int g    = lane >> 2;
    const int t    = lane & 3;
    const int m0   = (w & 3) * 16;
    const int n0   = (w >> 2) * 32;

    float acc[4][4];
#pragma unroll
    for (int nt = 0; nt < 4; nt++)
#pragma unroll
        for (int c = 0; c < 4; c++) acc[nt][c] = 0.0f;

#pragma unroll
    for (int k0 = 0; k0 < 64; k0 += 8) {
        uint2 a0 = A[(m0 + g)     * S2 + k0 + t];
        uint2 a1 = A[(m0 + g + 8) * S2 + k0 + t];
        uint2 a2 = A[(m0 + g)     * S2 + k0 + t + 4];
        uint2 a3 = A[(m0 + g + 8) * S2 + k0 + t + 4];
        uint2 b0[4], b1[4];
#pragma unroll
        for (int nt = 0; nt < 4; nt++) {
            const int nc = n0 + nt * 8 + g;
            b0[nt] = B[(k0 + t)     * S2 + nc];
            b1[nt] = B[(k0 + t + 4) * S2 + nc];
        }
        // hi*hi
#pragma unroll
        for (int nt = 0; nt < 4; nt++)
            mma_tf32(acc[nt][0], acc[nt][1], acc[nt][2], acc[nt][3],
                     a0.x, a1.x, a2.x, a3.x, b0[nt].x, b1[nt].x);
        // hi*lo
#pragma unroll
        for (int nt = 0; nt < 4; nt++)
            mma_tf32(acc[nt][0], acc[nt][1], acc[nt][2], acc[nt][3],
                     a0.x, a1.x, a2.x, a3.x, b0[nt].y, b1[nt].y);
        // lo*hi
#pragma unroll
        for (int nt = 0; nt < 4; nt++)
            mma_tf32(acc[nt][0], acc[nt][1], acc[nt][2], acc[nt][3],
                     a0.y, a1.y, a2.y, a3.y, b0[nt].x, b1[nt].x);
    }

#pragma unroll
    for (int nt = 0; nt < 4; nt++) {
        const int col = n0 + nt * 8 + 2 * t;
        if (WPS) {
            uint2 p0 = split2(acc[nt][0]), p1 = split2(acc[nt][1]);
            uint2 p2 = split2(acc[nt][2]), p3 = split2(acc[nt][3]);
            *(uint4*)(Cps + (m0 + g)     * S2 + col) = make_uint4(p0.x, p0.y, p1.x, p1.y);
            *(uint4*)(Cps + (m0 + g + 8) * S2 + col) = make_uint4(p2.x, p2.y, p3.x, p3.y);
        }
        if (WF) {
            *(float2*)(Cf + (m0 + g)     * CS + col) = make_float2(acc[nt][0], acc[nt][1]);
            *(float2*)(Cf + (m0 + g + 8) * CS + col) = make_float2(acc[nt][2], acc[nt][3]);
        }
    }
}

// ---------------------------------------------------------------------------
// Kernel 1: expm. Block b computes G[b] = expm(P_b^T - P_b) (presplit output).
// Order-9 Taylor (Paterson-Stockmeyer) + scaling/squaring. Seeds M[0]=M[1]=I.
// Dynamic smem: 5 * MATU2 uint2 = 174,080 B.
// ---------------------------------------------------------------------------
__global__ void __launch_bounds__(256, 1)
expm_kernel(const float* __restrict__ prim_raw) {
    extern __shared__ uint2 usm[];
    uint2* Bb = usm;
    uint2* B2 = usm + MATU2;
    uint2* B3 = usm + 2 * MATU2;
    uint2* X  = usm + 3 * MATU2;
    uint2* Y  = usm + 4 * MATU2;
    __shared__ float colsum[64];
    __shared__ int s_sh;

    const int b = blockIdx.x;
    const int tid = threadIdx.x;
    const float* P = prim_raw + b * MSZ;

    for (int tidx = tid; tidx < MSZ; tidx += 256) {
        int i = tidx >> 6, j = tidx & 63;
        Bb[i * S2 + j] = split2(P[j * 64 + i] - P[tidx]);
    }
    __syncthreads();

    if (tid < 64) {
        float s = 0.0f;
        for (int i = 0; i < 64; i++) s += fabsf(joinf(Bb[i * S2 + tid]));
        colsum[tid] = s;
    }
    __syncthreads();
    if (tid == 0) {
        float nm = 0.0f;
        for (int j = 0; j < 64; j++) nm = fmaxf(nm, colsum[j]);
        int s = 0;
        while (nm > 1.4f && s < 14) { nm *= 0.5f; s++; }
        s_sh = s;
    }
    __syncthreads();
    const int s = s_sh;
    const float scale = ldexpf(1.0f, -s);
    // scaling by 2^-s is exact on both tf32 components
    for (int tidx = tid; tidx < MSZ; tidx += 256) {
        int i = tidx >> 6, j = tidx & 63;
        uint2 v = Bb[i * S2 + j];
        v.x = __float_as_uint(__uint_as_float(v.x) * scale);
        v.y = __float_as_uint(__uint_as_float(v.y) * scale);
        Bb[i * S2 + j] = v;
    }
    __syncthreads();

    mm64ps<true, false>(B2, nullptr, 0, Bb, Bb);
    __syncthreads();
    mm64ps<true, false>(B3, nullptr, 0, Bb, B2);
    __syncthreads();

    // X = I/720 + B/5040 + B2/40320 + B3/362880
    for (int tidx = tid; tidx < MSZ; tidx += 256) {
        int i = tidx >> 6, j = tidx & 63;
        int k = i * S2 + j;
        float d = (i == j) ? (1.0f / 720.0f) : 0.0f;
        X[k] = split2(d + joinf(Bb[k]) * (1.0f / 5040.0f)
                        + joinf(B2[k]) * (1.0f / 40320.0f)
                        + joinf(B3[k]) * (1.0f / 362880.0f));
    }
    __syncthreads();
    mm64ps<true, false>(Y, nullptr, 0, B3, X);
    __syncthreads();
    for (int tidx = tid; tidx < MSZ; tidx += 256) {
        int i = tidx >> 6, j = tidx & 63;
        int k = i * S2 + j;
        float d = (i == j) ? (1.0f / 6.0f) : 0.0f;
        X[k] = split2(d + joinf(Bb[k]) * (1.0f / 24.0f)
                        + joinf(B2[k]) * (1.0f / 120.0f) + joinf(Y[k]));
    }
    __syncthreads();
    mm64ps<true, false>(Y, nullptr, 0, B3, X);
    __syncthreads();
    for (int tidx = tid; tidx < MSZ; tidx += 256) {
        int i = tidx >> 6, j = tidx & 63;
        int k = i * S2 + j;
        float d = (i == j) ? 1.0f : 0.0f;
        X[k] = split2(d + joinf(Bb[k]) + joinf(B2[k]) * 0.5f + joinf(Y[k]));
    }
    __syncthreads();

    uint2* Xp = X;
    uint2* Yp = Y;
    for (int k = 0; k < s; k++) {
        mm64ps<true, false>(Yp, nullptr, 0, Xp, Xp);
        __syncthreads();
        uint2* tp = Xp; Xp = Yp; Yp = tp;
    }

    for (int tidx = tid; tidx < MSZ; tidx += 256) {
        int i = tidx >> 6, j = tidx & 63;
        g_Gu2[b * MSZ + tidx] = Xp[i * S2 + j];
        g_M[b * MSZ + tidx] = (i == j) ? 1.0f : 0.0f;   // M[0], M[1] = I
    }
}

// ---------------------------------------------------------------------------
// Kernel 2: M[p] for p in [2,64): chain of <=4 matmuls on presplit G.
// Emits fp32 (g_M) and presplit (g_Mu2). Smem: 4 * MATU2 uint2 = 139,264 B.
// ---------------------------------------------------------------------------
__global__ void __launch_bounds__(256, 1)
table_small_kernel() {
    extern __shared__ uint2 usm[];
    uint2* G0 = usm;
    uint2* G1 = usm + MATU2;
    uint2* S0 = usm + 2 * MATU2;
    uint2* S1 = usm + 3 * MATU2;
    const int p = blockIdx.x + 2;
    const int tid = threadIdx.x;
    const int m = 32 - __clz(p);

    for (int tidx = tid; tidx < MSZ; tidx += 256) {
        int i = tidx >> 6, j = tidx & 63;
        G0[i * S2 + j] = g_Gu2[tidx];
        G1[i * S2 + j] = g_Gu2[MSZ + tidx];
    }
    __syncthreads();

    uint2* Xp = (p & 1) ? G1 : G0;
    uint2* scratch = S0;
    for (int st = 1; st <= m - 2; st++) {
        uint2* Gb = ((p >> st) & 1) ? G1 : G0;
        mm64ps<true, false>(scratch, nullptr, 0, Xp, Gb);
        __syncthreads();
        Xp = scratch;
        scratch = (scratch == S0) ? S1 : S0;
    }

    for (int tidx = tid; tidx < MSZ; tidx += 256) {
        int i = tidx >> 6, j = tidx & 63;
        uint2 v = Xp[i * S2 + j];
        g_Mu2[(size_t)p * MSZ + tidx] = v;
        g_M[(size_t)p * MSZ + tidx] = joinf(v);
    }
}

// ---------------------------------------------------------------------------
// Kernel 3: M[p] for p in [64,2048): M[p] = M[32|(p&31)] @ M[p>>5].
// Stages presplit operands from g_Mu2, result fp32 straight to g_M.
// Smem: 2 * MATU2 uint2 = 69,632 B.
// ---------------------------------------------------------------------------
__global__ void __launch_bounds__(256, 1)
table_big_kernel() {
    extern __shared__ uint2 usm[];
    uint2* Aps = usm;
    uint2* Bps = usm + MATU2;
    const int p = blockIdx.x + 64;
    const int tid = threadIdx.x;
    const uint2* ML = g_Mu2 + (size_t)((p & 31) | 32) * MSZ;
    const uint2* MR = g_Mu2 + (size_t)(p >> 5) * MSZ;

    for (int tidx = tid; tidx < MSZ; tidx += 256) {
        int i = tidx >> 6, j = tidx & 63;
        Aps[i * S2 + j] = __ldg(&ML[tidx]);
        Bps[i * S2 + j] = __ldg(&MR[tidx]);
    }
    __syncthreads();
    mm64ps<false, true>(nullptr, g_M + (size_t)p * MSZ, 64, Aps, Bps);
}

// ---------------------------------------------------------------------------
// Kernel 4: gather (copy) + content embedding.
// ---------------------------------------------------------------------------
__global__ void __launch_bounds__(256, 1)
gather_kernel(const int* __restrict__ token_types,
              const int* __restrict__ token_values,
              const int* __restrict__ node_positions,
              const float* __restrict__ embed_table,
              float* __restrict__ out,
              int maps_off) {
    const int token = blockIdx.x;
    const int tid = threadIdx.x;
    const int p = node_positions[token];

    const float4* src = (const float4*)(g_M + (size_t)p * MSZ);
    float4* dst = (float4*)(out + (size_t)maps_off + (size_t)token * MSZ);
    float4 v[4];
#pragma unroll
    for (int i = 0; i < 4; i++) v[i] = __ldg(&src[tid + i * 256]);
#pragma unroll
    for (int i = 0; i < 4; i++) __stcs(&dst[tid + i * 256], v[i]);

    if (tid < 64) {
        const int T = token_types[token];
        const int V = token_values[token];
        int idx;
        bool valid = true;
        if (T == 0)      idx = 0;
        else if (T == 1) idx = V + 1;
        else if (T == 2) idx = V + 5;
        else if (T == 4) idx = 8;
        else if (T == 3 && V == -1) idx = 10;
        else { idx = 0; valid = false; }
        out[(size_t)token * 64 + tid] = valid ? embed_table[idx * 64 + tid] : 0.0f;
    }
}

// ---------------------------------------------------------------------------
extern "C" void kernel_launch(void* const* d_in, const int* in_sizes, int n_in,
                              void* d_out, int out_size) {
    const int*   token_types  = (const int*)d_in[0];
    const int*   token_values = (const int*)d_in[1];
    const int*   node_pos     = (const int*)d_in[2];
    const float* embed_table  = (const float*)d_in[3];
    const float* prim_raw     = (const float*)d_in[4];
    float* out = (float*)d_out;

    const int n_tokens = in_sizes[0];
    const int maps_off = n_tokens * 64;

    cudaFuncSetAttribute(expm_kernel,
                         cudaFuncAttributeMaxDynamicSharedMemorySize, 5 * MATU2 * 8);
    cudaFuncSetAttribute(table_small_kernel,
                         cudaFuncAttributeMaxDynamicSharedMemorySize, 4 * MATU2 * 8);
    cudaFuncSetAttribute(table_big_kernel,
                         cudaFuncAttributeMaxDynamicSharedMemorySize, 2 * MATU2 * 8);

    expm_kernel<<<2, 256, 5 * MATU2 * 8>>>(prim_raw);
    table_small_kernel<<<62, 256, 4 * MATU2 * 8>>>();
    table_big_kernel<<<NPOS - 64, 256, 2 * MATU2 * 8>>>();
    gather_kernel<<<n_tokens, 256>>>(token_types, token_values, node_pos,
                                     embed_table, out, maps_off);
}

// round 5
// speedup vs baseline: 1.4722x; 1.3237x over previous
#include <cuda_runtime.h>
#include <cuda_bf16.h>
#include <math.h>

// ---------------------------------------------------------------------------
// TokenEmbedding: content embeddings + positional maps via binary-path
// products of two orthogonal generators G[b] = expm(P_b^T - P_b).
//
// expm + table_small: 3xTF32 mma.sync, presplit uint2 operands, 512 threads.
// table_big:          3xBF16 mma.sync m16n8k16, pre-packed bf16x2 operands.
//
// Output layout (float32):
//   [0, n_tokens*64)   content [B,S,64]
//   [n_tokens*64, ...) maps    [B,S,64,64]
// ---------------------------------------------------------------------------

#define NPOS 2048
#define MSZ  4096              // 64*64 elements per matrix
#define S2   68                // tf32 smem row stride in uint2 elements
#define MATU2 (64 * S2)        // uint2 per smem matrix (34,816 B)
#define SBF  36                // bf16 smem row stride in uint32 (packed pairs)

__device__ __align__(16) float g_M[NPOS * MSZ];       // fp32 table (32 MB)
__device__ __align__(16) uint2 g_Gu2[2 * MSZ];        // presplit tf32 generators
// bf16x2-packed table entries [64][2048]: A-layout (row-major, k-paired) and
// B-layout (col/n-major, k-paired), hi and lo components.
__device__ __align__(16) unsigned g_TAh[64 * 2048];
__device__ __align__(16) unsigned g_TAl[64 * 2048];
__device__ __align__(16) unsigned g_TBh[64 * 2048];
__device__ __align__(16) unsigned g_TBl[64 * 2048];

// ---------------------------------------------------------------------------
__device__ __forceinline__ unsigned f2tf32(float x) {
    unsigned r;
    asm("cvt.rna.tf32.f32 %0, %1;" : "=r"(r) : "f"(x));
    return r;
}
__device__ __forceinline__ uint2 split2(float f) {
    unsigned h = f2tf32(f);
    return make_uint2(h, f2tf32(f - __uint_as_float(h)));
}
__device__ __forceinline__ float joinf(uint2 v) {
    return __uint_as_float(v.x) + __uint_as_float(v.y);
}
__device__ __forceinline__ unsigned packbf(float e, float o) {
    __nv_bfloat162 h;
    h.x = __float2bfloat16_rn(e);   // low half = even-k element
    h.y = __float2bfloat16_rn(o);
    return *(unsigned*)&h;
}

__device__ __forceinline__ void mma_tf32(float& c0, float& c1, float& c2, float& c3,
                                         unsigned a0, unsigned a1, unsigned a2, unsigned a3,
                                         unsigned b0, unsigned b1) {
    asm volatile(
        "mma.sync.aligned.m16n8k8.row.col.f32.tf32.tf32.f32 "
        "{%0,%1,%2,%3}, {%4,%5,%6,%7}, {%8,%9}, {%0,%1,%2,%3};\n"
        : "+f"(c0), "+f"(c1), "+f"(c2), "+f"(c3)
        : "r"(a0), "r"(a1), "r"(a2), "r"(a3), "r"(b0), "r"(b1));
}
__device__ __forceinline__ void mma_bf16(float& c0, float& c1, float& c2, float& c3,
                                         unsigned a0, unsigned a1, unsigned a2, unsigned a3,
                                         unsigned b0, unsigned b1) {
    asm volatile(
        "mma.sync.aligned.m16n8k16.row.col.f32.bf16.bf16.f32 "
        "{%0,%1,%2,%3}, {%4,%5,%6,%7}, {%8,%9}, {%0,%1,%2,%3};\n"
        : "+f"(c0), "+f"(c1), "+f"(c2), "+f"(c3)
        : "r"(a0), "r"(a1), "r"(a2), "r"(a3), "r"(b0), "r"(b1));
}

// ---------------------------------------------------------------------------
// 64x64x64 3xTF32 matmul, presplit uint2 smem operands (stride S2).
// WARPS = 8 or 16. Warp w -> rows (w&3)*16.., cols (w>>2)*(NT*8)..
// WPS: presplit out to Cps (stride S2). Caller syncs.
// ---------------------------------------------------------------------------
template<int WARPS>
__device__ __forceinline__ void mm64ps(uint2* __restrict__ Cps,
                                       const uint2* __restrict__ A,
                                       const uint2* __restrict__ B) {
    constexpr int NT = 32 / WARPS * 4 / 4;   // 8 warps -> 4 tiles, 16 -> 2
    const int lane = threadIdx.x & 31;
    const int w    = threadIdx.x >> 5;
    const int g    = lane >> 2;
    const int t    = lane & 3;
    const int m0   = (w & 3) * 16;
    const int n0   = (w >> 2) * (NT * 8);

    float acc[NT][4];
#pragma unroll
    for (int nt = 0; nt < NT; nt++)
#pragma unroll
        for (int c = 0; c < 4; c++) acc[nt][c] = 0.0f;

#pragma unroll
    for (int k0 = 0; k0 < 64; k0 += 8) {
        uint2 a0 = A[(m0 + g)     * S2 + k0 + t];
        uint2 a1 = A[(m0 + g + 8) * S2 + k0 + t];
        uint2 a2 = A[(m0 + g)     * S2 + k0 + t + 4];
        uint2 a3 = A[(m0 + g + 8) * S2 + k0 + t + 4];
        uint2 b0[NT], b1[NT];
#pragma unroll
        for (int nt = 0; nt < NT; nt++) {
            const int nc = n0 + nt * 8 + g;
            b0[nt] = B[(k0 + t)     * S2 + nc];
            b1[nt] = B[(k0 + t + 4) * S2 + nc];
        }
#pragma unroll
        for (int nt = 0; nt < NT; nt++)
            mma_tf32(acc[nt][0], acc[nt][1], acc[nt][2], acc[nt][3],
                     a0.x, a1.x, a2.x, a3.x, b0[nt].x, b1[nt].x);
#pragma unroll
        for (int nt = 0; nt < NT; nt++)
            mma_tf32(acc[nt][0], acc[nt][1], acc[nt][2], acc[nt][3],
                     a0.x, a1.x, a2.x, a3.x, b0[nt].y, b1[nt].y);
#pragma unroll
        for (int nt = 0; nt < NT; nt++)
            mma_tf32(acc[nt][0], acc[nt][1], acc[nt][2], acc[nt][3],
                     a0.y, a1.y, a2.y, a3.y, b0[nt].x, b1[nt].x);
    }

#pragma unroll
    for (int nt = 0; nt < NT; nt++) {
        const int col = n0 + nt * 8 + 2 * t;
        uint2 p0 = split2(acc[nt][0]), p1 = split2(acc[nt][1]);
        uint2 p2 = split2(acc[nt][2]), p3 = split2(acc[nt][3]);
        *(uint4*)(Cps + (m0 + g)     * S2 + col) = make_uint4(p0.x, p0.y, p1.x, p1.y);
        *(uint4*)(Cps + (m0 + g + 8) * S2 + col) = make_uint4(p2.x, p2.y, p3.x, p3.y);
    }
}

// ---------------------------------------------------------------------------
// Kernel 1: expm. Block b computes G[b] = expm(P_b^T - P_b) (presplit output).
// 512 threads. Order-9 Taylor (PS) + scaling/squaring. Seeds M[0]=M[1]=I.
// Dynamic smem: 5 * MATU2 uint2 = 174,080 B.
// ---------------------------------------------------------------------------
__global__ void __launch_bounds__(512, 1)
expm_kernel(const float* __restrict__ prim_raw) {
    extern __shared__ uint2 usm[];
    uint2* Bb = usm;
    uint2* B2 = usm + MATU2;
    uint2* B3 = usm + 2 * MATU2;
    uint2* X  = usm + 3 * MATU2;
    uint2* Y  = usm + 4 * MATU2;
    __shared__ float colsum[64];
    __shared__ int s_sh;

    const int b = blockIdx.x;
    const int tid = threadIdx.x;
    const float* P = prim_raw + b * MSZ;

    for (int tidx = tid; tidx < MSZ; tidx += 512) {
        int i = tidx >> 6, j = tidx & 63;
        Bb[i * S2 + j] = split2(P[j * 64 + i] - P[tidx]);
    }
    __syncthreads();

    if (tid < 64) {
        float s = 0.0f;
        for (int i = 0; i < 64; i++) s += fabsf(joinf(Bb[i * S2 + tid]));
        colsum[tid] = s;
    }
    __syncthreads();
    if (tid == 0) {
        float nm = 0.0f;
        for (int j = 0; j < 64; j++) nm = fmaxf(nm, colsum[j]);
        int s = 0;
        while (nm > 1.4f && s < 14) { nm *= 0.5f; s++; }
        s_sh = s;
    }
    __syncthreads();
    const int s = s_sh;
    const float scale = ldexpf(1.0f, -s);
    for (int tidx = tid; tidx < MSZ; tidx += 512) {
        int i = tidx >> 6, j = tidx & 63;
        uint2 v = Bb[i * S2 + j];
        v.x = __float_as_uint(__uint_as_float(v.x) * scale);
        v.y = __float_as_uint(__uint_as_float(v.y) * scale);
        Bb[i * S2 + j] = v;
    }
    __syncthreads();

    mm64ps<16>(B2, Bb, Bb);
    __syncthreads();
    mm64ps<16>(B3, Bb, B2);
    __syncthreads();

    for (int tidx = tid; tidx < MSZ; tidx += 512) {
        int i = tidx >> 6, j = tidx & 63;
        int k = i * S2 + j;
        float d = (i == j) ? (1.0f / 720.0f) : 0.0f;
        X[k] = split2(d + joinf(Bb[k]) * (1.0f / 5040.0f)
                        + joinf(B2[k]) * (1.0f / 40320.0f)
                        + joinf(B3[k]) * (1.0f / 362880.0f));
    }
    __syncthreads();
    mm64ps<16>(Y, B3, X);
    __syncthreads();
    for (int tidx = tid; tidx < MSZ; tidx += 512) {
        int i = tidx >> 6, j = tidx & 63;
        int k = i * S2 + j;
        float d = (i == j) ? (1.0f / 6.0f) : 0.0f;
        X[k] = split2(d + joinf(Bb[k]) * (1.0f / 24.0f)
                        + joinf(B2[k]) * (1.0f / 120.0f) + joinf(Y[k]));
    }
    __syncthreads();
    mm64ps<16>(Y, B3, X);
    __syncthreads();
    for (int tidx = tid; tidx < MSZ; tidx += 512) {
        int i = tidx >> 6, j = tidx & 63;
        int k = i * S2 + j;
        float d = (i == j) ? 1.0f : 0.0f;
        X[k] = split2(d + joinf(Bb[k]) + joinf(B2[k]) * 0.5f + joinf(Y[k]));
    }
    __syncthreads();

    uint2* Xp = X;
    uint2* Yp = Y;
    for (int k = 0; k < s; k++) {
        mm64ps<16>(Yp, Xp, Xp);
        __syncthreads();
        uint2* tp = Xp; Xp = Yp; Yp = tp;
    }

    for (int tidx = tid; tidx < MSZ; tidx += 512) {
        int i = tidx >> 6, j = tidx & 63;
        g_Gu2[b * MSZ + tidx] = Xp[i * S2 + j];
        g_M[b * MSZ + tidx] = (i == j) ? 1.0f : 0.0f;   // M[0], M[1] = I
    }
}

// ---------------------------------------------------------------------------
// Kernel 2: M[p] for p in [2,64): chain of <=4 tf32 matmuls (512 threads).
// Emits fp32 g_M[p] plus bf16x2-packed A-layout / B-layout hi/lo tables.
// Dynamic smem: 4 * MATU2 uint2 = 139,264 B.
// ---------------------------------------------------------------------------
__global__ void __launch_bounds__(512, 1)
table_small_kernel() {
    extern __shared__ uint2 usm[];
    uint2* G0 = usm;
    uint2* G1 = usm + MATU2;
    uint2* S0 = usm + 2 * MATU2;
    uint2* S1 = usm + 3 * MATU2;
    const int p = blockIdx.x + 2;
    const int tid = threadIdx.x;
    const int m = 32 - __clz(p);

    for (int tidx = tid; tidx < MSZ; tidx += 512) {
        int i = tidx >> 6, j = tidx & 63;
        G0[i * S2 + j] = g_Gu2[tidx];
        G1[i * S2 + j] = g_Gu2[MSZ + tidx];
    }
    __syncthreads();

    uint2* Xp = (p & 1) ? G1 : G0;
    uint2* scratch = S0;
    for (int st = 1; st <= m - 2; st++) {
        uint2* Gb = ((p >> st) & 1) ? G1 : G0;
        mm64ps<16>(scratch, Xp, Gb);
        __syncthreads();
        Xp = scratch;
        scratch = (scratch == S0) ? S1 : S0;
    }

    // fp32 table entry
    for (int tidx = tid; tidx < MSZ; tidx += 512) {
        int i = tidx >> 6, j = tidx & 63;
        g_M[(size_t)p * MSZ + tidx] = joinf(Xp[i * S2 + j]);
    }
    // A-layout bf16x2 pack: [row i][kp j2] = (X[i][2j2], X[i][2j2+1])
    for (int q = tid; q < 2048; q += 512) {
        int i = q >> 5, j2 = q & 31;
        float e = joinf(Xp[i * S2 + 2 * j2]);
        float o = joinf(Xp[i * S2 + 2 * j2 + 1]);
        float he = __bfloat162float(__float2bfloat16_rn(e));
        float ho = __bfloat162float(__float2bfloat16_rn(o));
        g_TAh[p * 2048 + q] = packbf(he, ho);
        g_TAl[p * 2048 + q] = packbf(e - he, o - ho);
    }
    // B-layout bf16x2 pack: [col j][kp i2] = (X[2i2][j], X[2i2+1][j])
    for (int q = tid; q < 2048; q += 512) {
        int j = q >> 5, i2 = q & 31;
        float e = joinf(Xp[(2 * i2)     * S2 + j]);
        float o = joinf(Xp[(2 * i2 + 1) * S2 + j]);
        float he = __bfloat162float(__float2bfloat16_rn(e));
        float ho = __bfloat162float(__float2bfloat16_rn(o));
        g_TBh[p * 2048 + q] = packbf(he, ho);
        g_TBl[p * 2048 + q] = packbf(e - he, o - ho);
    }
}

// ---------------------------------------------------------------------------
// Kernel 3: M[p] for p in [64,2048): M[p] = M[32|(p&31)] @ M[p>>5].
// 3xBF16 mma m16n8k16 on pre-packed operands; fp32 result straight to g_M.
// Static smem: 4 * 64*36*4 = 36,864 B.
// ---------------------------------------------------------------------------
__global__ void __launch_bounds__(256, 1)
table_big_kernel() {
    __shared__ unsigned Ah[64 * SBF], Al[64 * SBF];
    __shared__ unsigned Bh[64 * SBF], Bl[64 * SBF];
    const int p = blockIdx.x + 64;
    const int tid = threadIdx.x;
    const int lo = (p & 31) | 32;
    const int hi = p >> 5;

    const uint4* gAh = (const uint4*)(g_TAh + (size_t)lo * 2048);
    const uint4* gAl = (const uint4*)(g_TAl + (size_t)lo * 2048);
    const uint4* gBh = (const uint4*)(g_TBh + (size_t)hi * 2048);
    const uint4* gBl = (const uint4*)(g_TBl + (size_t)hi * 2048);
#pragma unroll
    for (int it = 0; it < 2; it++) {
        int idx = tid + it * 256;            // 0..511 uint4 per array
        int row = idx >> 3;
        int c4  = (idx & 7) << 2;
        *(uint4*)(Ah + row * SBF + c4) = __ldg(&gAh[idx]);
        *(uint4*)(Al + row * SBF + c4) = __ldg(&gAl[idx]);
        *(uint4*)(Bh + row * SBF + c4) = __ldg(&gBh[idx]);
        *(uint4*)(Bl + row * SBF + c4) = __ldg(&gBl[idx]);
    }
    __syncthreads();

    const int lane = tid & 31;
    const int w    = tid >> 5;
    const int g    = lane >> 2;
    const int t    = lane & 3;
    const int m0   = (w & 3) * 16;
    const int n0   = (w >> 2) * 32;

    float acc[4][4];
#pragma unroll
    for (int nt = 0; nt < 4; nt++)
#pragma unroll
        for (int c = 0; c < 4; c++) acc[nt][c] = 0.0f;

#pragma unroll
    for (int ks = 0; ks < 4; ks++) {         // k16 steps
        const int kp0 = ks * 8;
        unsigned a0h = Ah[(m0 + g)     * SBF + kp0 + t];
        unsigned a1h = Ah[(m0 + g + 8) * SBF + kp0 + t];
        unsigned a2h = Ah[(m0 + g)     * SBF + kp0 + t + 4];
        unsigned a3h = Ah[(m0 + g + 8) * SBF + kp0 + t + 4];
        unsigned a0l = Al[(m0 + g)     * SBF + kp0 + t];
        unsigned a1l = Al[(m0 + g + 8) * SBF + kp0 + t];
        unsigned a2l = Al[(m0 + g)     * SBF + kp0 + t + 4];
        unsigned a3l = Al[(m0 + g + 8) * SBF + kp0 + t + 4];
        unsigned b0h[4], b1h[4], b0l[4], b1l[4];
#pragma unroll
        for (int nt = 0; nt < 4; nt++) {
            const int nc = n0 + nt * 8 + g;
            b0h[nt] = Bh[nc * SBF + kp0 + t];
            b1h[nt] = Bh[nc * SBF + kp0 + t + 4];
            b0l[nt] = Bl[nc * SBF + kp0 + t];
            b1l[nt] = Bl[nc * SBF + kp0 + t + 4];
        }
#pragma unroll
        for (int nt = 0; nt < 4; nt++)
            mma_bf16(acc[nt][0], acc[nt][1], acc[nt][2], acc[nt][3],
                     a0h, a1h, a2h, a3h, b0h[nt], b1h[nt]);
#pragma unroll
        for (int nt = 0; nt < 4; nt++)
            mma_bf16(acc[nt][0], acc[nt][1], acc[nt][2], acc[nt][3],
                     a0h, a1h, a2h, a3h, b0l[nt], b1l[nt]);
#pragma unroll
        for (int nt = 0; nt < 4; nt++)
            mma_bf16(acc[nt][0], acc[nt][1], acc[nt][2], acc[nt][3],
                     a0l, a1l, a2l, a3l, b0h[nt], b1h[nt]);
    }

    float* Cf = g_M + (size_t)p * MSZ;
#pragma unroll
    for (int nt = 0; nt < 4; nt++) {
        const int col = n0 + nt * 8 + 2 * t;
        *(float2*)(Cf + (m0 + g)     * 64 + col) = make_float2(acc[nt][0], acc[nt][1]);
        *(float2*)(Cf + (m0 + g + 8) * 64 + col) = make_float2(acc[nt][2], acc[nt][3]);
    }
}

// ---------------------------------------------------------------------------
// Kernel 4: gather (copy) + content embedding.
// ---------------------------------------------------------------------------
__global__ void __launch_bounds__(256, 1)
gather_kernel(const int* __restrict__ token_types,
              const int* __restrict__ token_values,
              const int* __restrict__ node_positions,
              const float* __restrict__ embed_table,
              float* __restrict__ out,
              int maps_off) {
    const int token = blockIdx.x;
    const int tid = threadIdx.x;
    const int p = node_positions[token];

    const float4* src = (const float4*)(g_M + (size_t)p * MSZ);
    float4* dst = (float4*)(out + (size_t)maps_off + (size_t)token * MSZ);
    float4 v[4];
#pragma unroll
    for (int i = 0; i < 4; i++) v[i] = __ldg(&src[tid + i * 256]);
#pragma unroll
    for (int i = 0; i < 4; i++) __stcs(&dst[tid + i * 256], v[i]);

    if (tid < 64) {
        const int T = token_types[token];
        const int V = token_values[token];
        int idx;
        bool valid = true;
        if (T == 0)      idx = 0;
        else if (T == 1) idx = V + 1;
        else if (T == 2) idx = V + 5;
        else if (T == 4) idx = 8;
        else if (T == 3 && V == -1) idx = 10;
        else { idx = 0; valid = false; }
        out[(size_t)token * 64 + tid] = valid ? embed_table[idx * 64 + tid] : 0.0f;
    }
}

// ---------------------------------------------------------------------------
extern "C" void kernel_launch(void* const* d_in, const int* in_sizes, int n_in,
                              void* d_out, int out_size) {
    const int*   token_types  = (const int*)d_in[0];
    const int*   token_values = (const int*)d_in[1];
    const int*   node_pos     = (const int*)d_in[2];
    const float* embed_table  = (const float*)d_in[3];
    const float* prim_raw     = (const float*)d_in[4];
    float* out = (float*)d_out;

    const int n_tokens = in_sizes[0];
    const int maps_off = n_tokens * 64;

    cudaFuncSetAttribute(expm_kernel,
                         cudaFuncAttributeMaxDynamicSharedMemorySize, 5 * MATU2 * 8);
    cudaFuncSetAttribute(table_small_kernel,
                         cudaFuncAttributeMaxDynamicSharedMemorySize, 4 * MATU2 * 8);

    expm_kernel<<<2, 512, 5 * MATU2 * 8>>>(prim_raw);
    table_small_kernel<<<62, 512, 4 * MATU2 * 8>>>();
    table_big_kernel<<<NPOS - 64, 256>>>();
    gather_kernel<<<n_tokens, 256>>>(token_types, token_values, node_pos,
                                     embed_table, out, maps_off);
}

// round 6
// speedup vs baseline: 1.6463x; 1.1183x over previous
#include <cuda_runtime.h>
#include <cuda_bf16.h>
#include <math.h>

// ---------------------------------------------------------------------------
// TokenEmbedding, scatter-fused:
//   expm (tf32 presplit)  -> G[0..1]
//   table_small (+CSR)    -> M[2..63] (fp32 + bf16-packed), pos->token CSR
//   emit                  -> scatter blocks: M[p>=64] = M[lo]@M[hi] (bf16 3x)
//                            streamed straight into every token slot;
//                            small blocks: content embeds + p<64 map copies
//
// Output layout (float32):
//   [0, n_tokens*64)   content [B,S,64]
//   [n_tokens*64, ...) maps    [B,S,64,64]
// ---------------------------------------------------------------------------

#define NPOS 2048
#define MSZ  4096              // 64*64 elements per matrix
#define S2   68                // tf32 smem row stride in uint2 elements
#define MATU2 (64 * S2)        // uint2 per smem matrix (34,816 B)
#define SBF  36                // bf16 smem row stride in uint32 (packed pairs)
#define MAXTOK 8192

__device__ __align__(16) float g_M[64 * MSZ];     // fp32 table p<64 (1 MB)
__device__ __align__(16) uint2 g_Gu2[2 * MSZ];    // presplit tf32 generators
// bf16x2-packed table entries [64][2048]: A-layout (row-major, k-paired) and
// B-layout (n-major, k-paired), hi and lo components.
__device__ __align__(16) unsigned g_TAh[64 * 2048];
__device__ __align__(16) unsigned g_TAl[64 * 2048];
__device__ __align__(16) unsigned g_TBh[64 * 2048];
__device__ __align__(16) unsigned g_TBl[64 * 2048];
// position -> token CSR
__device__ int g_off[NPOS + 1];
__device__ int g_tok[MAXTOK];

// ---------------------------------------------------------------------------
__device__ __forceinline__ unsigned f2tf32(float x) {
    unsigned r;
    asm("cvt.rna.tf32.f32 %0, %1;" : "=r"(r) : "f"(x));
    return r;
}
__device__ __forceinline__ uint2 split2(float f) {
    unsigned h = f2tf32(f);
    return make_uint2(h, f2tf32(f - __uint_as_float(h)));
}
__device__ __forceinline__ float joinf(uint2 v) {
    return __uint_as_float(v.x) + __uint_as_float(v.y);
}
__device__ __forceinline__ unsigned packbf(float e, float o) {
    __nv_bfloat162 h;
    h.x = __float2bfloat16_rn(e);
    h.y = __float2bfloat16_rn(o);
    return *(unsigned*)&h;
}

__device__ __forceinline__ void mma_tf32(float& c0, float& c1, float& c2, float& c3,
                                         unsigned a0, unsigned a1, unsigned a2, unsigned a3,
                                         unsigned b0, unsigned b1) {
    asm volatile(
        "mma.sync.aligned.m16n8k8.row.col.f32.tf32.tf32.f32 "
        "{%0,%1,%2,%3}, {%4,%5,%6,%7}, {%8,%9}, {%0,%1,%2,%3};\n"
        : "+f"(c0), "+f"(c1), "+f"(c2), "+f"(c3)
        : "r"(a0), "r"(a1), "r"(a2), "r"(a3), "r"(b0), "r"(b1));
}
__device__ __forceinline__ void mma_bf16(float& c0, float& c1, float& c2, float& c3,
                                         unsigned a0, unsigned a1, unsigned a2, unsigned a3,
                                         unsigned b0, unsigned b1) {
    asm volatile(
        "mma.sync.aligned.m16n8k16.row.col.f32.bf16.bf16.f32 "
        "{%0,%1,%2,%3}, {%4,%5,%6,%7}, {%8,%9}, {%0,%1,%2,%3};\n"
        : "+f"(c0), "+f"(c1), "+f"(c2), "+f"(c3)
        : "r"(a0), "r"(a1), "r"(a2), "r"(a3), "r"(b0), "r"(b1));
}

// ---------------------------------------------------------------------------
// 64x64x64 3xTF32 matmul, presplit uint2 smem operands (stride S2), 16 warps.
// ---------------------------------------------------------------------------
__device__ __forceinline__ void mm64ps16(uint2* __restrict__ Cps,
                                         const uint2* __restrict__ A,
                                         const uint2* __restrict__ B) {
    const int lane = threadIdx.x & 31;
    const int w    = threadIdx.x >> 5;
    const int g    = lane >> 2;
    const int t    = lane & 3;
    const int m0   = (w & 3) * 16;
    const int n0   = (w >> 2) * 16;

    float acc[2][4];
#pragma unroll
    for (int nt = 0; nt < 2; nt++)
#pragma unroll
        for (int c = 0; c < 4; c++) acc[nt][c] = 0.0f;

#pragma unroll
    for (int k0 = 0; k0 < 64; k0 += 8) {
        uint2 a0 = A[(m0 + g)     * S2 + k0 + t];
        uint2 a1 = A[(m0 + g + 8) * S2 + k0 + t];
        uint2 a2 = A[(m0 + g)     * S2 + k0 + t + 4];
        uint2 a3 = A[(m0 + g + 8) * S2 + k0 + t + 4];
        uint2 b0[2], b1[2];
#pragma unroll
        for (int nt = 0; nt < 2; nt++) {
            const int nc = n0 + nt * 8 + g;
            b0[nt] = B[(k0 + t)     * S2 + nc];
            b1[nt] = B[(k0 + t + 4) * S2 + nc];
        }
#pragma unroll
        for (int nt = 0; nt < 2; nt++)
            mma_tf32(acc[nt][0], acc[nt][1], acc[nt][2], acc[nt][3],
                     a0.x, a1.x, a2.x, a3.x, b0[nt].x, b1[nt].x);
#pragma unroll
        for (int nt = 0; nt < 2; nt++)
            mma_tf32(acc[nt][0], acc[nt][1], acc[nt][2], acc[nt][3],
                     a0.x, a1.x, a2.x, a3.x, b0[nt].y, b1[nt].y);
#pragma unroll
        for (int nt = 0; nt < 2; nt++)
            mma_tf32(acc[nt][0], acc[nt][1], acc[nt][2], acc[nt][3],
                     a0.y, a1.y, a2.y, a3.y, b0[nt].x, b1[nt].x);
    }

#pragma unroll
    for (int nt = 0; nt < 2; nt++) {
        const int col = n0 + nt * 8 + 2 * t;
        uint2 p0 = split2(acc[nt][0]), p1 = split2(acc[nt][1]);
        uint2 p2 = split2(acc[nt][2]), p3 = split2(acc[nt][3]);
        *(uint4*)(Cps + (m0 + g)     * S2 + col) = make_uint4(p0.x, p0.y, p1.x, p1.y);
        *(uint4*)(Cps + (m0 + g + 8) * S2 + col) = make_uint4(p2.x, p2.y, p3.x, p3.y);
    }
}

// ---------------------------------------------------------------------------
// Kernel 1: expm (512 threads/block, 2 blocks). Seeds M[0]=M[1]=I.
// ---------------------------------------------------------------------------
__global__ void __launch_bounds__(512, 1)
expm_kernel(const float* __restrict__ prim_raw) {
    extern __shared__ uint2 usm[];
    uint2* Bb = usm;
    uint2* B2 = usm + MATU2;
    uint2* B3 = usm + 2 * MATU2;
    uint2* X  = usm + 3 * MATU2;
    uint2* Y  = usm + 4 * MATU2;
    __shared__ float colsum[64];
    __shared__ int s_sh;

    const int b = blockIdx.x;
    const int tid = threadIdx.x;
    const float* P = prim_raw + b * MSZ;

    for (int tidx = tid; tidx < MSZ; tidx += 512) {
        int i = tidx >> 6, j = tidx & 63;
        Bb[i * S2 + j] = split2(P[j * 64 + i] - P[tidx]);
    }
    __syncthreads();

    if (tid < 64) {
        float s = 0.0f;
        for (int i = 0; i < 64; i++) s += fabsf(joinf(Bb[i * S2 + tid]));
        colsum[tid] = s;
    }
    __syncthreads();
    if (tid == 0) {
        float nm = 0.0f;
        for (int j = 0; j < 64; j++) nm = fmaxf(nm, colsum[j]);
        int s = 0;
        while (nm > 1.4f && s < 14) { nm *= 0.5f; s++; }
        s_sh = s;
    }
    __syncthreads();
    const int s = s_sh;
    const float scale = ldexpf(1.0f, -s);
    for (int tidx = tid; tidx < MSZ; tidx += 512) {
        int i = tidx >> 6, j = tidx & 63;
        uint2 v = Bb[i * S2 + j];
        v.x = __float_as_uint(__uint_as_float(v.x) * scale);
        v.y = __float_as_uint(__uint_as_float(v.y) * scale);
        Bb[i * S2 + j] = v;
    }
    __syncthreads();

    mm64ps16(B2, Bb, Bb);
    __syncthreads();
    mm64ps16(B3, Bb, B2);
    __syncthreads();

    for (int tidx = tid; tidx < MSZ; tidx += 512) {
        int i = tidx >> 6, j = tidx & 63;
        int k = i * S2 + j;
        float d = (i == j) ? (1.0f / 720.0f) : 0.0f;
        X[k] = split2(d + joinf(Bb[k]) * (1.0f / 5040.0f)
                        + joinf(B2[k]) * (1.0f / 40320.0f)
                        + joinf(B3[k]) * (1.0f / 362880.0f));
    }
    __syncthreads();
    mm64ps16(Y, B3, X);
    __syncthreads();
    for (int tidx = tid; tidx < MSZ; tidx += 512) {
        int i = tidx >> 6, j = tidx & 63;
        int k = i * S2 + j;
        float d = (i == j) ? (1.0f / 6.0f) : 0.0f;
        X[k] = split2(d + joinf(Bb[k]) * (1.0f / 24.0f)
                        + joinf(B2[k]) * (1.0f / 120.0f) + joinf(Y[k]));
    }
    __syncthreads();
    mm64ps16(Y, B3, X);
    __syncthreads();
    for (int tidx = tid; tidx < MSZ; tidx += 512) {
        int i = tidx >> 6, j = tidx & 63;
        int k = i * S2 + j;
        float d = (i == j) ? 1.0f : 0.0f;
        X[k] = split2(d + joinf(Bb[k]) + joinf(B2[k]) * 0.5f + joinf(Y[k]));
    }
    __syncthreads();

    uint2* Xp = X;
    uint2* Yp = Y;
    for (int k = 0; k < s; k++) {
        mm64ps16(Yp, Xp, Xp);
        __syncthreads();
        uint2* tp = Xp; Xp = Yp; Yp = tp;
    }

    for (int tidx = tid; tidx < MSZ; tidx += 512) {
        int i = tidx >> 6, j = tidx & 63;
        g_Gu2[b * MSZ + tidx] = Xp[i * S2 + j];
        g_M[b * MSZ + tidx] = (i == j) ? 1.0f : 0.0f;   // M[0], M[1] = I
    }
}

// ---------------------------------------------------------------------------
// Kernel 2: blocks 0..61 -> M[p], p in [2,64) (tf32 chain; emits fp32 +
// bf16-packed tables). Block 62 -> pos->token CSR.
// ---------------------------------------------------------------------------
__global__ void __launch_bounds__(512, 1)
table_small_kernel(const int* __restrict__ node_positions, int n_tokens) {
    extern __shared__ uint2 usm[];

    if (blockIdx.x == 62) {
        // --- CSR build: counts -> exclusive scan -> fill ---
        int* cnt = (int*)usm;           // [NPOS]
        int* off = cnt + NPOS;          // [NPOS]
        const int tid = threadIdx.x;
        const int lane = tid & 31;
        const int wid = tid >> 5;
        __shared__ int wpart[16];

        for (int i = tid; i < NPOS; i += 512) cnt[i] = 0;
        __syncthreads();
        for (int t = tid; t < n_tokens; t += 512)
            atomicAdd(&cnt[node_positions[t]], 1);
        __syncthreads();

        // 512 threads x 4 entries each: block exclusive scan
        int base = tid * 4;
        int c0 = cnt[base], c1 = cnt[base + 1], c2 = cnt[base + 2], c3 = cnt[base + 3];
        int sum = c0 + c1 + c2 + c3;
        int inc = sum;
#pragma unroll
        for (int d = 1; d < 32; d <<= 1) {
            int v = __shfl_up_sync(0xffffffff, inc, d);
            if (lane >= d) inc += v;
        }
        if (lane == 31) wpart[wid] = inc;
        __syncthreads();
        if (wid == 0) {
            int v = (lane < 16) ? wpart[lane] : 0;
#pragma unroll
            for (int d = 1; d < 16; d <<= 1) {
                int u = __shfl_up_sync(0xffffffff, v, d);
                if (lane >= d) v += u;
            }
            if (lane < 16) wpart[lane] = v;
        }
        __syncthreads();
        int excl = inc - sum + ((wid > 0) ? wpart[wid - 1] : 0);
        off[base] = excl;
        off[base + 1] = excl + c0;
        off[base + 2] = excl + c0 + c1;
        off[base + 3] = excl + c0 + c1 + c2;
        __syncthreads();
        for (int i = tid; i < NPOS; i += 512) g_off[i] = off[i];
        if (tid == 0) g_off[NPOS] = n_tokens;
        // fill (order within a position irrelevant)
        for (int t = tid; t < n_tokens; t += 512) {
            int p = node_positions[t];
            int slot = atomicSub(&cnt[p], 1) - 1;
            g_tok[off[p] + slot] = t;
        }
        return;
    }

    uint2* G0 = usm;
    uint2* G1 = usm + MATU2;
    uint2* S0 = usm + 2 * MATU2;
    uint2* S1 = usm + 3 * MATU2;
    const int p = blockIdx.x + 2;
    const int tid = threadIdx.x;
    const int m = 32 - __clz(p);

    for (int tidx = tid; tidx < MSZ; tidx += 512) {
        int i = tidx >> 6, j = tidx & 63;
        G0[i * S2 + j] = g_Gu2[tidx];
        G1[i * S2 + j] = g_Gu2[MSZ + tidx];
    }
    __syncthreads();

    uint2* Xp = (p & 1) ? G1 : G0;
    uint2* scratch = S0;
    for (int st = 1; st <= m - 2; st++) {
        uint2* Gb = ((p >> st) & 1) ? G1 : G0;
        mm64ps16(scratch, Xp, Gb);
        __syncthreads();
        Xp = scratch;
        scratch = (scratch == S0) ? S1 : S0;
    }

    for (int tidx = tid; tidx < MSZ; tidx += 512) {
        int i = tidx >> 6, j = tidx & 63;
        g_M[(size_t)p * MSZ + tidx] = joinf(Xp[i * S2 + j]);
    }
    for (int q = tid; q < 2048; q += 512) {
        int i = q >> 5, j2 = q & 31;
        float e = joinf(Xp[i * S2 + 2 * j2]);
        float o = joinf(Xp[i * S2 + 2 * j2 + 1]);
        float he = __bfloat162float(__float2bfloat16_rn(e));
        float ho = __bfloat162float(__float2bfloat16_rn(o));
        g_TAh[p * 2048 + q] = packbf(he, ho);
        g_TAl[p * 2048 + q] = packbf(e - he, o - ho);
    }
    for (int q = tid; q < 2048; q += 512) {
        int j = q >> 5, i2 = q & 31;
        float e = joinf(Xp[(2 * i2)     * S2 + j]);
        float o = joinf(Xp[(2 * i2 + 1) * S2 + j]);
        float he = __bfloat162float(__float2bfloat16_rn(e));
        float ho = __bfloat162float(__float2bfloat16_rn(o));
        g_TBh[p * 2048 + q] = packbf(he, ho);
        g_TBl[p * 2048 + q] = packbf(e - he, o - ho);
    }
}

// ---------------------------------------------------------------------------
// Kernel 3 (emit): blocks [0, NPOS-64): scatter — compute M[p]=M[lo]@M[hi]
// (3xBF16) and stream it into every token slot with that position (skip if
// no tokens). Blocks [NPOS-64, +ceil(n/8)): content embeddings for 8 tokens
// + map copies for tokens with p < 64.
// ---------------------------------------------------------------------------
__global__ void __launch_bounds__(256, 1)
emit_kernel(const int* __restrict__ token_types,
            const int* __restrict__ token_values,
            const int* __restrict__ node_positions,
            const float* __restrict__ embed_table,
            float* __restrict__ out,
            int maps_off, int n_tokens) {
    const int tid = threadIdx.x;

    if (blockIdx.x >= NPOS - 64) {
        // ----- small blocks: content + p<64 map copies -----
        const int t0 = (blockIdx.x - (NPOS - 64)) * 8;
        for (int i = tid; i < 512; i += 256) {
            const int token = t0 + (i >> 6);
            if (token >= n_tokens) break;
            const int lane = i & 63;
            const int T = token_types[token];
            const int V = token_values[token];
            int idx;
            bool valid = true;
            if (T == 0)      idx = 0;
            else if (T == 1) idx = V + 1;
            else if (T == 2) idx = V + 5;
            else if (T == 4) idx = 8;
            else if (T == 3 && V == -1) idx = 10;
            else { idx = 0; valid = false; }
            out[(size_t)token * 64 + lane] = valid ? embed_table[idx * 64 + lane] : 0.0f;
        }
#pragma unroll
        for (int k = 0; k < 8; k++) {
            const int token = t0 + k;
            if (token >= n_tokens) break;
            const int p = node_positions[token];
            if (p < 64) {
                const float4* src = (const float4*)(g_M + (size_t)p * MSZ);
                float4* dst = (float4*)(out + (size_t)maps_off + (size_t)token * MSZ);
#pragma unroll
                for (int j = 0; j < 4; j++)
                    __stcs(&dst[tid + j * 256], __ldg(&src[tid + j * 256]));
            }
        }
        return;
    }

    // ----- scatter blocks -----
    const int p = blockIdx.x + 64;
    const int beg = g_off[p];
    const int end = g_off[p + 1];
    if (beg == end) return;

    __shared__ unsigned Ah[64 * SBF], Al[64 * SBF];
    __shared__ unsigned Bh[64 * SBF], Bl[64 * SBF];
    const int lo = (p & 31) | 32;
    const int hi = p >> 5;

    const uint4* gAh = (const uint4*)(g_TAh + (size_t)lo * 2048);
    const uint4* gAl = (const uint4*)(g_TAl + (size_t)lo * 2048);
    const uint4* gBh = (const uint4*)(g_TBh + (size_t)hi * 2048);
    const uint4* gBl = (const uint4*)(g_TBl + (size_t)hi * 2048);
#pragma unroll
    for (int it = 0; it < 2; it++) {
        int idx = tid + it * 256;
        int row = idx >> 3;
        int c4  = (idx & 7) << 2;
        *(uint4*)(Ah + row * SBF + c4) = __ldg(&gAh[idx]);
        *(uint4*)(Al + row * SBF + c4) = __ldg(&gAl[idx]);
        *(uint4*)(Bh + row * SBF + c4) = __ldg(&gBh[idx]);
        *(uint4*)(Bl + row * SBF + c4) = __ldg(&gBl[idx]);
    }
    __syncthreads();

    const int lane = tid & 31;
    const int w    = tid >> 5;
    const int g    = lane >> 2;
    const int t    = lane & 3;
    const int m0   = (w & 3) * 16;
    const int n0   = (w >> 2) * 32;

    float acc[4][4];
#pragma unroll
    for (int nt = 0; nt < 4; nt++)
#pragma unroll
        for (int c = 0; c < 4; c++) acc[nt][c] = 0.0f;

#pragma unroll
    for (int ks = 0; ks < 4; ks++) {
        const int kp0 = ks * 8;
        unsigned a0h = Ah[(m0 + g)     * SBF + kp0 + t];
        unsigned a1h = Ah[(m0 + g + 8) * SBF + kp0 + t];
        unsigned a2h = Ah[(m0 + g)     * SBF + kp0 + t + 4];
        unsigned a3h = Ah[(m0 + g + 8) * SBF + kp0 + t + 4];
        unsigned a0l = Al[(m0 + g)     * SBF + kp0 + t];
        unsigned a1l = Al[(m0 + g + 8) * SBF + kp0 + t];
        unsigned a2l = Al[(m0 + g)     * SBF + kp0 + t + 4];
        unsigned a3l = Al[(m0 + g + 8) * SBF + kp0 + t + 4];
        unsigned b0h[4], b1h[4], b0l[4], b1l[4];
#pragma unroll
        for (int nt = 0; nt < 4; nt++) {
            const int nc = n0 + nt * 8 + g;
            b0h[nt] = Bh[nc * SBF + kp0 + t];
            b1h[nt] = Bh[nc * SBF + kp0 + t + 4];
            b0l[nt] = Bl[nc * SBF + kp0 + t];
            b1l[nt] = Bl[nc * SBF + kp0 + t + 4];
        }
#pragma unroll
        for (int nt = 0; nt < 4; nt++)
            mma_bf16(acc[nt][0], acc[nt][1], acc[nt][2], acc[nt][3],
                     a0h, a1h, a2h, a3h, b0h[nt], b1h[nt]);
#pragma unroll
        for (int nt = 0; nt < 4; nt++)
            mma_bf16(acc[nt][0], acc[nt][1], acc[nt][2], acc[nt][3],
                     a0h, a1h, a2h, a3h, b0l[nt], b1l[nt]);
#pragma unroll
        for (int nt = 0; nt < 4; nt++)
            mma_bf16(acc[nt][0], acc[nt][1], acc[nt][2], acc[nt][3],
                     a0l, a1l, a2l, a3l, b0h[nt], b1h[nt]);
    }

    for (int e = beg; e < end; e++) {
        float* Cf = out + (size_t)maps_off + (size_t)g_tok[e] * MSZ;
#pragma unroll
        for (int nt = 0; nt < 4; nt++) {
            const int col = n0 + nt * 8 + 2 * t;
            __stcs((float2*)(Cf + (m0 + g)     * 64 + col),
                   make_float2(acc[nt][0], acc[nt][1]));
            __stcs((float2*)(Cf + (m0 + g + 8) * 64 + col),
                   make_float2(acc[nt][2], acc[nt][3]));
        }
    }
}

// ---------------------------------------------------------------------------
extern "C" void kernel_launch(void* const* d_in, const int* in_sizes, int n_in,
                              void* d_out, int out_size) {
    const int*   token_types  = (const int*)d_in[0];
    const int*   token_values = (const int*)d_in[1];
    const int*   node_pos     = (const int*)d_in[2];
    const float* embed_table  = (const float*)d_in[3];
    const float* prim_raw     = (const float*)d_in[4];
    float* out = (float*)d_out;

    const int n_tokens = in_sizes[0];
    const int maps_off = n_tokens * 64;
    const int n_small_blocks = (n_tokens + 7) / 8;

    cudaFuncSetAttribute(expm_kernel,
                         cudaFuncAttributeMaxDynamicSharedMemorySize, 5 * MATU2 * 8);
    cudaFuncSetAttribute(table_small_kernel,
                         cudaFuncAttributeMaxDynamicSharedMemorySize, 4 * MATU2 * 8);

    expm_kernel<<<2, 512, 5 * MATU2 * 8>>>(prim_raw);
    table_small_kernel<<<63, 512, 4 * MATU2 * 8>>>(node_pos, n_tokens);
    emit_kernel<<<(NPOS - 64) + n_small_blocks, 256>>>(
        token_types, token_values, node_pos, embed_table, out,
        maps_off, n_tokens);
}

// round 7
// speedup vs baseline: 1.6565x; 1.0062x over previous
#include <cuda_runtime.h>
#include <cuda_bf16.h>
#include <math.h>

// ---------------------------------------------------------------------------
// TokenEmbedding, scatter-fused:
//   expm (tf32 presplit, fused epilogues) -> G[0..1]
//   table_small (+CSR)  -> M[2..63] (fp32 + bf16-packed), pos->token CSR
//   emit                -> scatter blocks: M[p>=64] = M[lo]@M[hi] (bf16 3x)
//                          streamed straight into every token slot;
//                          small blocks: content embeds + p<64 map copies
//
// Output layout (float32):
//   [0, n_tokens*64)   content [B,S,64]
//   [n_tokens*64, ...) maps    [B,S,64,64]
// ---------------------------------------------------------------------------

#define NPOS 2048
#define MSZ  4096              // 64*64 elements per matrix
#define S2   68                // tf32 smem row stride in uint2 elements
#define MATU2 (64 * S2)        // uint2 per smem matrix (34,816 B)
#define SBF  36                // bf16 smem row stride in uint32 (packed pairs)
#define MAXTOK 8192

__device__ __align__(16) float g_M[64 * MSZ];     // fp32 table p<64 (1 MB)
__device__ __align__(16) uint2 g_Gu2[2 * MSZ];    // presplit tf32 generators
__device__ __align__(16) unsigned g_TAh[64 * 2048];
__device__ __align__(16) unsigned g_TAl[64 * 2048];
__device__ __align__(16) unsigned g_TBh[64 * 2048];
__device__ __align__(16) unsigned g_TBl[64 * 2048];
__device__ int g_off[NPOS + 1];
__device__ int g_tok[MAXTOK];

// ---------------------------------------------------------------------------
__device__ __forceinline__ unsigned f2tf32(float x) {
    unsigned r;
    asm("cvt.rna.tf32.f32 %0, %1;" : "=r"(r) : "f"(x));
    return r;
}
__device__ __forceinline__ uint2 split2(float f) {
    unsigned h = f2tf32(f);
    return make_uint2(h, f2tf32(f - __uint_as_float(h)));
}
__device__ __forceinline__ float joinf(uint2 v) {
    return __uint_as_float(v.x) + __uint_as_float(v.y);
}
__device__ __forceinline__ unsigned packbf(float e, float o) {
    __nv_bfloat162 h;
    h.x = __float2bfloat16_rn(e);
    h.y = __float2bfloat16_rn(o);
    return *(unsigned*)&h;
}

__device__ __forceinline__ void mma_tf32(float& c0, float& c1, float& c2, float& c3,
                                         unsigned a0, unsigned a1, unsigned a2, unsigned a3,
                                         unsigned b0, unsigned b1) {
    asm volatile(
        "mma.sync.aligned.m16n8k8.row.col.f32.tf32.tf32.f32 "
        "{%0,%1,%2,%3}, {%4,%5,%6,%7}, {%8,%9}, {%0,%1,%2,%3};\n"
        : "+f"(c0), "+f"(c1), "+f"(c2), "+f"(c3)
        : "r"(a0), "r"(a1), "r"(a2), "r"(a3), "r"(b0), "r"(b1));
}
__device__ __forceinline__ void mma_bf16(float& c0, float& c1, float& c2, float& c3,
                                         unsigned a0, unsigned a1, unsigned a2, unsigned a3,
                                         unsigned b0, unsigned b1) {
    asm volatile(
        "mma.sync.aligned.m16n8k16.row.col.f32.bf16.bf16.f32 "
        "{%0,%1,%2,%3}, {%4,%5,%6,%7}, {%8,%9}, {%0,%1,%2,%3};\n"
        : "+f"(c0), "+f"(c1), "+f"(c2), "+f"(c3)
        : "r"(a0), "r"(a1), "r"(a2), "r"(a3), "r"(b0), "r"(b1));
}

// ---------------------------------------------------------------------------
// MMA core: 64x64x64 3xTF32 accumulate into acc[2][4]; presplit uint2 smem
// operands (stride S2); 16 warps, warp -> rows m0..m0+16, cols n0..n0+16.
// ---------------------------------------------------------------------------
__device__ __forceinline__ void mmacc16(float (&acc)[2][4],
                                        const uint2* __restrict__ A,
                                        const uint2* __restrict__ B,
                                        int m0, int n0, int g, int t) {
#pragma unroll
    for (int nt = 0; nt < 2; nt++)
#pragma unroll
        for (int c = 0; c < 4; c++) acc[nt][c] = 0.0f;

#pragma unroll
    for (int k0 = 0; k0 < 64; k0 += 8) {
        uint2 a0 = A[(m0 + g)     * S2 + k0 + t];
        uint2 a1 = A[(m0 + g + 8) * S2 + k0 + t];
        uint2 a2 = A[(m0 + g)     * S2 + k0 + t + 4];
        uint2 a3 = A[(m0 + g + 8) * S2 + k0 + t + 4];
        uint2 b0[2], b1[2];
#pragma unroll
        for (int nt = 0; nt < 2; nt++) {
            const int nc = n0 + nt * 8 + g;
            b0[nt] = B[(k0 + t)     * S2 + nc];
            b1[nt] = B[(k0 + t + 4) * S2 + nc];
        }
#pragma unroll
        for (int nt = 0; nt < 2; nt++)
            mma_tf32(acc[nt][0], acc[nt][1], acc[nt][2], acc[nt][3],
                     a0.x, a1.x, a2.x, a3.x, b0[nt].x, b1[nt].x);
#pragma unroll
        for (int nt = 0; nt < 2; nt++)
            mma_tf32(acc[nt][0], acc[nt][1], acc[nt][2], acc[nt][3],
                     a0.x, a1.x, a2.x, a3.x, b0[nt].y, b1[nt].y);
#pragma unroll
        for (int nt = 0; nt < 2; nt++)
            mma_tf32(acc[nt][0], acc[nt][1], acc[nt][2], acc[nt][3],
                     a0.y, a1.y, a2.y, a3.y, b0[nt].x, b1[nt].x);
    }
}

// Plain split-store epilogue.
__device__ __forceinline__ void epi_split(uint2* __restrict__ C,
                                          const float (&acc)[2][4],
                                          int m0, int n0, int g, int t) {
#pragma unroll
    for (int nt = 0; nt < 2; nt++) {
        const int c0 = n0 + nt * 8 + 2 * t;
#pragma unroll
        for (int rr = 0; rr < 2; rr++) {
            const int r = m0 + g + rr * 8;
            uint2 s0 = split2(acc[nt][rr * 2]), s1 = split2(acc[nt][rr * 2 + 1]);
            *(uint4*)(C + r * S2 + c0) = make_uint4(s0.x, s0.y, s1.x, s1.y);
        }
    }
}

// Fused Horner epilogue: Xout = k0d*I + k1*Bb + k2*B2 + k3*acc (split-stored).
// Optionally also split-stores raw acc into Rout (for B3).
__device__ __forceinline__ void epi_poly(uint2* __restrict__ Xout,
                                         uint2* __restrict__ Rout,
                                         const uint2* __restrict__ Bb,
                                         const uint2* __restrict__ B2,
                                         const float (&acc)[2][4],
                                         float k0d, float k1, float k2, float k3,
                                         int m0, int n0, int g, int t) {
#pragma unroll
    for (int nt = 0; nt < 2; nt++) {
        const int c0 = n0 + nt * 8 + 2 * t;
#pragma unroll
        for (int rr = 0; rr < 2; rr++) {
            const int r = m0 + g + rr * 8;
            const float v0 = acc[nt][rr * 2], v1 = acc[nt][rr * 2 + 1];
            if (Rout) {
                uint2 q0 = split2(v0), q1 = split2(v1);
                *(uint4*)(Rout + r * S2 + c0) = make_uint4(q0.x, q0.y, q1.x, q1.y);
            }
            float p0 = ((r == c0)     ? k0d : 0.0f)
                     + joinf(Bb[r * S2 + c0])     * k1
                     + joinf(B2[r * S2 + c0])     * k2 + k3 * v0;
            float p1 = ((r == c0 + 1) ? k0d : 0.0f)
                     + joinf(Bb[r * S2 + c0 + 1]) * k1
                     + joinf(B2[r * S2 + c0 + 1]) * k2 + k3 * v1;
            uint2 s0 = split2(p0), s1 = split2(p1);
            *(uint4*)(Xout + r * S2 + c0) = make_uint4(s0.x, s0.y, s1.x, s1.y);
        }
    }
}

// Full matmul + split store (used by table_small chains).
__device__ __forceinline__ void mm64ps16(uint2* __restrict__ Cps,
                                         const uint2* __restrict__ A,
                                         const uint2* __restrict__ B) {
    const int lane = threadIdx.x & 31;
    const int w    = threadIdx.x >> 5;
    const int g    = lane >> 2;
    const int t    = lane & 3;
    float acc[2][4];
    mmacc16(acc, A, B, (w & 3) * 16, (w >> 2) * 16, g, t);
    epi_split(Cps, acc, (w & 3) * 16, (w >> 2) * 16, g, t);
}

// ---------------------------------------------------------------------------
// Kernel 1: expm (512 threads/block, 2 blocks), fused epilogues, deferred
// scaling (B2/B3 computed unscaled; 2^-ks folded into Horner coefficients).
// Order-9 Taylor + s squarings. Seeds M[0]=M[1]=I.
// ---------------------------------------------------------------------------
__global__ void __launch_bounds__(512, 1)
expm_kernel(const float* __restrict__ prim_raw) {
    extern __shared__ uint2 usm[];
    uint2* Bb = usm;               // unscaled split(A)
    uint2* B2 = usm + MATU2;       // A^2 (unscaled)
    uint2* B3 = usm + 2 * MATU2;   // A^3 (unscaled)
    uint2* X  = usm + 3 * MATU2;
    uint2* Y  = usm + 4 * MATU2;
    __shared__ float colsum[64];
    __shared__ int s_sh;

    const int b = blockIdx.x;
    const int tid = threadIdx.x;
    const float* P = prim_raw + b * MSZ;

    const int lane = tid & 31;
    const int w    = tid >> 5;
    const int g    = lane >> 2;
    const int t    = lane & 3;
    const int m0   = (w & 3) * 16;
    const int n0   = (w >> 2) * 16;

    if (tid < 64) colsum[tid] = 0.0f;
    __syncthreads();

    // Stage split(A) and accumulate column 1-norms in one pass.
    for (int tidx = tid; tidx < MSZ; tidx += 512) {
        int i = tidx >> 6, j = tidx & 63;
        float a = P[j * 64 + i] - P[tidx];
        Bb[i * S2 + j] = split2(a);
        atomicAdd(&colsum[j], fabsf(a));
    }
    __syncthreads();

    if (tid == 0) {
        float nm = 0.0f;
        for (int j = 0; j < 64; j++) nm = fmaxf(nm, colsum[j]);
        int s = 0;
        while (nm > 1.4f && s < 14) { nm *= 0.5f; s++; }
        s_sh = s;
    }

    float acc[2][4];

    // B2 = A@A
    mmacc16(acc, Bb, Bb, m0, n0, g, t);
    epi_split(B2, acc, m0, n0, g, t);
    __syncthreads();    // also publishes s_sh

    const int s = s_sh;
    const float sig  = ldexpf(1.0f, -s);
    const float sig2 = sig * sig;
    const float sig3 = sig2 * sig;

    // B3 = A@B2 ; X = I/720 + (sig/5040)A + (sig2/40320)B2 + (sig3/362880)B3
    mmacc16(acc, Bb, B2, m0, n0, g, t);
    epi_poly(X, B3, Bb, B2, acc,
             1.0f / 720.0f, sig / 5040.0f, sig2 / 40320.0f, sig3 / 362880.0f,
             m0, n0, g, t);
    __syncthreads();

    // Y = I/6 + (sig/24)A + (sig2/120)B2 + sig3*(B3@X)
    mmacc16(acc, B3, X, m0, n0, g, t);
    epi_poly(Y, nullptr, Bb, B2, acc,
             1.0f / 6.0f, sig / 24.0f, sig2 / 120.0f, sig3, m0, n0, g, t);
    __syncthreads();

    // X = I + sig*A + (sig2/2)B2 + sig3*(B3@Y)
    mmacc16(acc, B3, Y, m0, n0, g, t);
    epi_poly(X, nullptr, Bb, B2, acc,
             1.0f, sig, sig2 * 0.5f, sig3, m0, n0, g, t);
    __syncthreads();

    // s squarings
    uint2* Xp = X;
    uint2* Yp = Y;
    for (int k = 0; k < s; k++) {
        mmacc16(acc, Xp, Xp, m0, n0, g, t);
        epi_split(Yp, acc, m0, n0, g, t);
        __syncthreads();
        uint2* tp = Xp; Xp = Yp; Yp = tp;
    }

    for (int tidx = tid; tidx < MSZ; tidx += 512) {
        int i = tidx >> 6, j = tidx & 63;
        g_Gu2[b * MSZ + tidx] = Xp[i * S2 + j];
        g_M[b * MSZ + tidx] = (i == j) ? 1.0f : 0.0f;   // M[0], M[1] = I
    }
}

// ---------------------------------------------------------------------------
// Kernel 2: blocks 0..61 -> M[p], p in [2,64) (tf32 chain; emits fp32 +
// bf16-packed tables). Block 62 -> pos->token CSR.
// ---------------------------------------------------------------------------
__global__ void __launch_bounds__(512, 1)
table_small_kernel(const int* __restrict__ node_positions, int n_tokens) {
    extern __shared__ uint2 usm[];

    if (blockIdx.x == 62) {
        int* cnt = (int*)usm;           // [NPOS]
        int* off = cnt + NPOS;          // [NPOS]
        const int tid = threadIdx.x;
        const int lane = tid & 31;
        const int wid = tid >> 5;
        __shared__ int wpart[16];

        for (int i = tid; i < NPOS; i += 512) cnt[i] = 0;
        __syncthreads();
        for (int t = tid; t < n_tokens; t += 512)
            atomicAdd(&cnt[node_positions[t]], 1);
        __syncthreads();

        int base = tid * 4;
        int c0 = cnt[base], c1 = cnt[base + 1], c2 = cnt[base + 2], c3 = cnt[base + 3];
        int sum = c0 + c1 + c2 + c3;
        int inc = sum;
#pragma unroll
        for (int d = 1; d < 32; d <<= 1) {
            int v = __shfl_up_sync(0xffffffff, inc, d);
            if (lane >= d) inc += v;
        }
        if (lane == 31) wpart[wid] = inc;
        __syncthreads();
        if (wid == 0) {
            int v = (lane < 16) ? wpart[lane] : 0;
#pragma unroll
            for (int d = 1; d < 16; d <<= 1) {
                int u = __shfl_up_sync(0xffffffff, v, d);
                if (lane >= d) v += u;
            }
            if (lane < 16) wpart[lane] = v;
        }
        __syncthreads();
        int excl = inc - sum + ((wid > 0) ? wpart[wid - 1] : 0);
        off[base] = excl;
        off[base + 1] = excl + c0;
        off[base + 2] = excl + c0 + c1;
        off[base + 3] = excl + c0 + c1 + c2;
        __syncthreads();
        for (int i = tid; i < NPOS; i += 512) g_off[i] = off[i];
        if (tid == 0) g_off[NPOS] = n_tokens;
        for (int t = tid; t < n_tokens; t += 512) {
            int p = node_positions[t];
            int slot = atomicSub(&cnt[p], 1) - 1;
            g_tok[off[p] + slot] = t;
        }
        return;
    }

    uint2* G0 = usm;
    uint2* G1 = usm + MATU2;
    uint2* S0 = usm + 2 * MATU2;
    uint2* S1 = usm + 3 * MATU2;
    const int p = blockIdx.x + 2;
    const int tid = threadIdx.x;
    const int m = 32 - __clz(p);

    for (int tidx = tid; tidx < MSZ; tidx += 512) {
        int i = tidx >> 6, j = tidx & 63;
        G0[i * S2 + j] = g_Gu2[tidx];
        G1[i * S2 + j] = g_Gu2[MSZ + tidx];
    }
    __syncthreads();

    uint2* Xp = (p & 1) ? G1 : G0;
    uint2* scratch = S0;
    for (int st = 1; st <= m - 2; st++) {
        uint2* Gb = ((p >> st) & 1) ? G1 : G0;
        mm64ps16(scratch, Xp, Gb);
        __syncthreads();
        Xp = scratch;
        scratch = (scratch == S0) ? S1 : S0;
    }

    for (int tidx = tid; tidx < MSZ; tidx += 512) {
        int i = tidx >> 6, j = tidx & 63;
        g_M[(size_t)p * MSZ + tidx] = joinf(Xp[i * S2 + j]);
    }
    for (int q = tid; q < 2048; q += 512) {
        int i = q >> 5, j2 = q & 31;
        float e = joinf(Xp[i * S2 + 2 * j2]);
        float o = joinf(Xp[i * S2 + 2 * j2 + 1]);
        float he = __bfloat162float(__float2bfloat16_rn(e));
        float ho = __bfloat162float(__float2bfloat16_rn(o));
        g_TAh[p * 2048 + q] = packbf(he, ho);
        g_TAl[p * 2048 + q] = packbf(e - he, o - ho);
    }
    for (int q = tid; q < 2048; q += 512) {
        int j = q >> 5, i2 = q & 31;
        float e = joinf(Xp[(2 * i2)     * S2 + j]);
        float o = joinf(Xp[(2 * i2 + 1) * S2 + j]);
        float he = __bfloat162float(__float2bfloat16_rn(e));
        float ho = __bfloat162float(__float2bfloat16_rn(o));
        g_TBh[p * 2048 + q] = packbf(he, ho);
        g_TBl[p * 2048 + q] = packbf(e - he, o - ho);
    }
}

// ---------------------------------------------------------------------------
// Kernel 3 (emit): blocks [0, NPOS-64): scatter — compute M[p]=M[lo]@M[hi]
// (3xBF16) and stream into every token slot with that position. Blocks
// [NPOS-64, +ceil(n/8)): content embeddings + p<64 map copies.
// ---------------------------------------------------------------------------
__global__ void __launch_bounds__(256, 1)
emit_kernel(const int* __restrict__ token_types,
            const int* __restrict__ token_values,
            const int* __restrict__ node_positions,
            const float* __restrict__ embed_table,
            float* __restrict__ out,
            int maps_off, int n_tokens) {
    const int tid = threadIdx.x;

    if (blockIdx.x >= NPOS - 64) {
        const int t0 = (blockIdx.x - (NPOS - 64)) * 8;
        for (int i = tid; i < 512; i += 256) {
            const int token = t0 + (i >> 6);
            if (token >= n_tokens) break;
            const int lane = i & 63;
            const int T = token_types[token];
            const int V = token_values[token];
            int idx;
            bool valid = true;
            if (T == 0)      idx = 0;
            else if (T == 1) idx = V + 1;
            else if (T == 2) idx = V + 5;
            else if (T == 4) idx = 8;
            else if (T == 3 && V == -1) idx = 10;
            else { idx = 0; valid = false; }
            out[(size_t)token * 64 + lane] = valid ? embed_table[idx * 64 + lane] : 0.0f;
        }
#pragma unroll
        for (int k = 0; k < 8; k++) {
            const int token = t0 + k;
            if (token >= n_tokens) break;
            const int p = node_positions[token];
            if (p < 64) {
                const float4* src = (const float4*)(g_M + (size_t)p * MSZ);
                float4* dst = (float4*)(out + (size_t)maps_off + (size_t)token * MSZ);
#pragma unroll
                for (int j = 0; j < 4; j++)
                    __stcs(&dst[tid + j * 256], __ldg(&src[tid + j * 256]));
            }
        }
        return;
    }

    const int p = blockIdx.x + 64;
    const int beg = g_off[p];
    const int end = g_off[p + 1];
    if (beg == end) return;

    __shared__ unsigned Ah[64 * SBF], Al[64 * SBF];
    __shared__ unsigned Bh[64 * SBF], Bl[64 * SBF];
    const int lo = (p & 31) | 32;
    const int hi = p >> 5;

    const uint4* gAh = (const uint4*)(g_TAh + (size_t)lo * 2048);
    const uint4* gAl = (const uint4*)(g_TAl + (size_t)lo * 2048);
    const uint4* gBh = (const uint4*)(g_TBh + (size_t)hi * 2048);
    const uint4* gBl = (const uint4*)(g_TBl + (size_t)hi * 2048);
#pragma unroll
    for (int it = 0; it < 2; it++) {
        int idx = tid + it * 256;
        int row = idx >> 3;
        int c4  = (idx & 7) << 2;
        *(uint4*)(Ah + row * SBF + c4) = __ldg(&gAh[idx]);
        *(uint4*)(Al + row * SBF + c4) = __ldg(&gAl[idx]);
        *(uint4*)(Bh + row * SBF + c4) = __ldg(&gBh[idx]);
        *(uint4*)(Bl + row * SBF + c4) = __ldg(&gBl[idx]);
    }
    __syncthreads();

    const int lane = tid & 31;
    const int w    = tid >> 5;
    const int g    = lane >> 2;
    const int t    = lane & 3;
    const int m0   = (w & 3) * 16;
    const int n0   = (w >> 2) * 32;

    float acc[4][4];
#pragma unroll
    for (int nt = 0; nt < 4; nt++)
#pragma unroll
        for (int c = 0; c < 4; c++) acc[nt][c] = 0.0f;

#pragma unroll
    for (int ks = 0; ks < 4; ks++) {
        const int kp0 = ks * 8;
        unsigned a0h = Ah[(m0 + g)     * SBF + kp0 + t];
        unsigned a1h = Ah[(m0 + g + 8) * SBF + kp0 + t];
        unsigned a2h = Ah[(m0 + g)     * SBF + kp0 + t + 4];
        unsigned a3h = Ah[(m0 + g + 8) * SBF + kp0 + t + 4];
        unsigned a0l = Al[(m0 + g)     * SBF + kp0 + t];
        unsigned a1l = Al[(m0 + g + 8) * SBF + kp0 + t];
        unsigned a2l = Al[(m0 + g)     * SBF + kp0 + t + 4];
        unsigned a3l = Al[(m0 + g + 8) * SBF + kp0 + t + 4];
        unsigned b0h[4], b1h[4], b0l[4], b1l[4];
#pragma unroll
        for (int nt = 0; nt < 4; nt++) {
            const int nc = n0 + nt * 8 + g;
            b0h[nt] = Bh[nc * SBF + kp0 + t];
            b1h[nt] = Bh[nc * SBF + kp0 + t + 4];
            b0l[nt] = Bl[nc * SBF + kp0 + t];
            b1l[nt] = Bl[nc * SBF + kp0 + t + 4];
        }
#pragma unroll
        for (int nt = 0; nt < 4; nt++)
            mma_bf16(acc[nt][0], acc[nt][1], acc[nt][2], acc[nt][3],
                     a0h, a1h, a2h, a3h, b0h[nt], b1h[nt]);
#pragma unroll
        for (int nt = 0; nt < 4; nt++)
            mma_bf16(acc[nt][0], acc[nt][1], acc[nt][2], acc[nt][3],
                     a0h, a1h, a2h, a3h, b0l[nt], b1l[nt]);
#pragma unroll
        for (int nt = 0; nt < 4; nt++)
            mma_bf16(acc[nt][0], acc[nt][1], acc[nt][2], acc[nt][3],
                     a0l, a1l, a2l, a3l, b0h[nt], b1h[nt]);
    }

    for (int e = beg; e < end; e++) {
        float* Cf = out + (size_t)maps_off + (size_t)g_tok[e] * MSZ;
#pragma unroll
        for (int nt = 0; nt < 4; nt++) {
            const int col = n0 + nt * 8 + 2 * t;
            __stcs((float2*)(Cf + (m0 + g)     * 64 + col),
                   make_float2(acc[nt][0], acc[nt][1]));
            __stcs((float2*)(Cf + (m0 + g + 8) * 64 + col),
                   make_float2(acc[nt][2], acc[nt][3]));
        }
    }
}

// ---------------------------------------------------------------------------
extern "C" void kernel_launch(void* const* d_in, const int* in_sizes, int n_in,
                              void* d_out, int out_size) {
    const int*   token_types  = (const int*)d_in[0];
    const int*   token_values = (const int*)d_in[1];
    const int*   node_pos     = (const int*)d_in[2];
    const float* embed_table  = (const float*)d_in[3];
    const float* prim_raw     = (const float*)d_in[4];
    float* out = (float*)d_out;

    const int n_tokens = in_sizes[0];
    const int maps_off = n_tokens * 64;
    const int n_small_blocks = (n_tokens + 7) / 8;

    cudaFuncSetAttribute(expm_kernel,
                         cudaFuncAttributeMaxDynamicSharedMemorySize, 5 * MATU2 * 8);
    cudaFuncSetAttribute(table_small_kernel,
                         cudaFuncAttributeMaxDynamicSharedMemorySize, 4 * MATU2 * 8);

    expm_kernel<<<2, 512, 5 * MATU2 * 8>>>(prim_raw);
    table_small_kernel<<<63, 512, 4 * MATU2 * 8>>>(node_pos, n_tokens);
    emit_kernel<<<(NPOS - 64) + n_small_blocks, 256>>>(
        token_types, token_values, node_pos, embed_table, out,
        maps_off, n_tokens);
}